// round 2
// baseline (speedup 1.0000x reference)
#include <cuda_runtime.h>
#include <cuda_bf16.h>
#include <math.h>

// Problem shape (fixed): B=16, Lq=Lk=2048, Dq=Dk=Dv=1024
#define BATCH 16
#define LQ 2048
#define LK 2048
#define DM 1024

#define BM 128
#define BN 128
#define BK 16
#define TM 8
#define TN 8
// 256 threads per CTA

// scratch: kt = tanh(K @ W^T), [B, Lk, Dq] fp32 = 134 MB
__device__ float g_kt[(size_t)BATCH * LK * DM];

// Generic batched SGEMM: C[M,N] = A[M,K] * op(B)
//   TRANSB=true : B is [N,K] row-major (NT gemm), ldb=K
//   TRANSB=false: B is [K,N] row-major (NN gemm), ldb=N
// A is [M,K] row-major, lda=K. C is [M,N] row-major, ldc=N.
// Dims must be multiples of tile sizes (they are for this problem).
template <bool TRANSB, bool TANH_EPI>
__global__ __launch_bounds__(256) void sgemm_kernel(
    const float* __restrict__ A, const float* __restrict__ Bm,
    float* __restrict__ C,
    int M, int N, int K,
    long strideA, long strideB, long strideC)
{
    __shared__ float As[BK][BM + 4];
    __shared__ float Bs[BK][BN + 4];

    const int bz = blockIdx.z;
    A  += (long)bz * strideA;
    Bm += (long)bz * strideB;
    C  += (long)bz * strideC;

    const int rowBlk = blockIdx.y * BM;
    const int colBlk = blockIdx.x * BN;
    const int tid = threadIdx.x;
    const int tm = (tid >> 4) * TM;   // 0..120
    const int tn = (tid & 15) * TN;   // 0..120

    float acc[TM][TN];
#pragma unroll
    for (int i = 0; i < TM; i++)
#pragma unroll
        for (int j = 0; j < TN; j++) acc[i][j] = 0.0f;

    for (int k0 = 0; k0 < K; k0 += BK) {
        // ---- load A tile [BM x BK], transpose into As[BK][BM] ----
#pragma unroll
        for (int i = 0; i < 2; i++) {
            int f4 = tid + i * 256;         // 0..511 float4 slots
            int r  = f4 >> 2;               // 0..127
            int c4 = (f4 & 3) << 2;         // 0,4,8,12
            float4 val = *reinterpret_cast<const float4*>(
                &A[(long)(rowBlk + r) * K + k0 + c4]);
            As[c4 + 0][r] = val.x;
            As[c4 + 1][r] = val.y;
            As[c4 + 2][r] = val.z;
            As[c4 + 3][r] = val.w;
        }
        // ---- load B tile into Bs[BK][BN] ----
        if (TRANSB) {
#pragma unroll
            for (int i = 0; i < 2; i++) {
                int f4 = tid + i * 256;
                int r  = f4 >> 2;           // n index 0..127
                int c4 = (f4 & 3) << 2;
                float4 val = *reinterpret_cast<const float4*>(
                    &Bm[(long)(colBlk + r) * K + k0 + c4]);
                Bs[c4 + 0][r] = val.x;
                Bs[c4 + 1][r] = val.y;
                Bs[c4 + 2][r] = val.z;
                Bs[c4 + 3][r] = val.w;
            }
        } else {
#pragma unroll
            for (int i = 0; i < 2; i++) {
                int f4 = tid + i * 256;     // 512 = 16 rows * 32 float4/row
                int r  = f4 >> 5;           // 0..15
                int c  = (f4 & 31) << 2;    // 0..124
                float4 val = *reinterpret_cast<const float4*>(
                    &Bm[(long)(k0 + r) * N + colBlk + c]);
                *reinterpret_cast<float4*>(&Bs[r][c]) = val;
            }
        }
        __syncthreads();

#pragma unroll
        for (int kk = 0; kk < BK; kk++) {
            float a[TM], b[TN];
#pragma unroll
            for (int i = 0; i < TM; i++) a[i] = As[kk][tm + i];
#pragma unroll
            for (int j = 0; j < TN; j++) b[j] = Bs[kk][tn + j];
#pragma unroll
            for (int i = 0; i < TM; i++)
#pragma unroll
                for (int j = 0; j < TN; j++)
                    acc[i][j] = fmaf(a[i], b[j], acc[i][j]);
        }
        __syncthreads();
    }

    // ---- epilogue: optional tanh, write C ----
#pragma unroll
    for (int i = 0; i < TM; i++) {
        long row = rowBlk + tm + i;
#pragma unroll
        for (int j = 0; j < TN; j += 4) {
            float4 v4;
            v4.x = acc[i][j + 0];
            v4.y = acc[i][j + 1];
            v4.z = acc[i][j + 2];
            v4.w = acc[i][j + 3];
            if (TANH_EPI) {
                v4.x = tanhf(v4.x);
                v4.y = tanhf(v4.y);
                v4.z = tanhf(v4.z);
                v4.w = tanhf(v4.w);
            }
            *reinterpret_cast<float4*>(&C[row * N + colBlk + tn + j]) = v4;
        }
    }
}

// Row softmax over att[B*Lq, Lk]: scale, mask (k_length_index==0 -> -1e9),
// subtract max, exp, normalize. One CTA of 256 threads per row; Lk=2048 -> 8/thread.
__global__ __launch_bounds__(256) void softmax_kernel(
    float* __restrict__ att, const int* __restrict__ kli)
{
    const int row = blockIdx.x;           // 0..B*Lq-1
    const int b = row >> 11;              // row / Lq (Lq = 2048)
    float* p = att + (long)row * LK;
    const int* m = kli + (long)b * LK;
    const int tid = threadIdx.x;
    const float scale = 0.03125f;         // 1024^-0.5

    float vals[8];
    float mx = -3.0e38f;
#pragma unroll
    for (int i = 0; i < 8; i++) {
        int c = tid + i * 256;
        float s = p[c] * scale;
        if (m[c] == 0) s = -1.0e9f;
        vals[i] = s;
        mx = fmaxf(mx, s);
    }

    __shared__ float red[8];
#pragma unroll
    for (int o = 16; o > 0; o >>= 1)
        mx = fmaxf(mx, __shfl_xor_sync(0xffffffffu, mx, o));
    if ((tid & 31) == 0) red[tid >> 5] = mx;
    __syncthreads();
    mx = red[0];
#pragma unroll
    for (int i = 1; i < 8; i++) mx = fmaxf(mx, red[i]);
    __syncthreads();   // before reusing red[] for the sum

    float sum = 0.0f;
#pragma unroll
    for (int i = 0; i < 8; i++) {
        vals[i] = expf(vals[i] - mx);
        sum += vals[i];
    }
#pragma unroll
    for (int o = 16; o > 0; o >>= 1)
        sum += __shfl_xor_sync(0xffffffffu, sum, o);
    if ((tid & 31) == 0) red[tid >> 5] = sum;
    __syncthreads();
    sum = 0.0f;
#pragma unroll
    for (int i = 0; i < 8; i++) sum += red[i];

    const float inv = 1.0f / sum;
#pragma unroll
    for (int i = 0; i < 8; i++)
        p[tid + i * 256] = vals[i] * inv;
}

extern "C" void kernel_launch(void* const* d_in, const int* in_sizes, int n_in,
                              void* d_out, int out_size)
{
    const float* q   = (const float*)d_in[0];   // [B, Lq, Dq]
    const float* k   = (const float*)d_in[1];   // [B, Lk, Dk]
    const float* v   = (const float*)d_in[2];   // [B, Lk, Dv]
    const int*   kli = (const int*)  d_in[3];   // [B, Lk]
    const float* W   = (const float*)d_in[4];   // [Dq, Dk]

    float* out = (float*)d_out;                            // [B, Lq, Dv]
    float* att = out + (size_t)BATCH * LQ * DM;            // [B, Lq, Lk]

    float* kt = nullptr;
    cudaGetSymbolAddress((void**)&kt, g_kt);

    // 1) kt = tanh(K @ W^T): M=Lk, N=Dq, K=Dk, NT, tanh epilogue. W shared across batch.
    sgemm_kernel<true, true><<<dim3(DM / BN, LK / BM, BATCH), 256>>>(
        k, W, kt, LK, DM, DM,
        (long)LK * DM, 0L, (long)LK * DM);

    // 2) scores = Q @ kt^T: M=Lq, N=Lk, K=Dq, NT, raw scores into att region.
    sgemm_kernel<true, false><<<dim3(LK / BN, LQ / BM, BATCH), 256>>>(
        q, kt, att, LQ, LK, DM,
        (long)LQ * DM, (long)LK * DM, (long)LQ * LK);

    // 3) softmax rows (scale + mask + softmax), in place on att.
    softmax_kernel<<<BATCH * LQ, 256>>>(att, kli);

    // 4) out = att @ V: M=Lq, N=Dv, K=Lk, NN.
    sgemm_kernel<false, false><<<dim3(DM / BN, LQ / BM, BATCH), 256>>>(
        att, v, out, LQ, DM, LK,
        (long)LQ * LK, (long)LK * DM, (long)LQ * DM);
}

// round 5
// speedup vs baseline: 2.2539x; 2.2539x over previous
#include <cuda_runtime.h>
#include <cuda_bf16.h>
#include <math.h>
#include <stdint.h>

// Problem shape (fixed): B=16, Lq=Lk=2048, Dq=Dk=Dv=1024
#define BATCH 16
#define LQ 2048
#define LK 2048
#define DM 1024

// GEMM tiling
#define BM 128
#define BN 128
#define BK 32
#define NTH 256

// smem layout: K-major tiles, row stride 40 halves (80 bytes) for conflict-free frags
#define ROWB 80
#define TILE_B (128 * ROWB)       // 10240
#define A_HI 0
#define A_LO TILE_B
#define B_HI (2 * TILE_B)
#define B_LO (3 * TILE_B)
#define STAGE (4 * TILE_B)        // 40960
#define DYN_SMEM (2 * STAGE)      // 81920

// scratch
__device__ float g_kt[(size_t)BATCH * LK * DM];                 // tanh(K W^T) fp32
__device__ __nv_bfloat16 g_vth[(size_t)BATCH * DM * LK];        // V^T hi bf16 [B, Dv, Lk]
__device__ __nv_bfloat16 g_vtl[(size_t)BATCH * DM * LK];        // V^T lo bf16

// fp32 -> (bf16 hi, bf16 lo) split, 4 elems packed into 2x u32 each
__device__ __forceinline__ void split4(float4 v, uint2& h, uint2& l) {
    __nv_bfloat16 h0 = __float2bfloat16(v.x);
    __nv_bfloat16 h1 = __float2bfloat16(v.y);
    __nv_bfloat16 h2 = __float2bfloat16(v.z);
    __nv_bfloat16 h3 = __float2bfloat16(v.w);
    __nv_bfloat16 l0 = __float2bfloat16(v.x - __bfloat162float(h0));
    __nv_bfloat16 l1 = __float2bfloat16(v.y - __bfloat162float(h1));
    __nv_bfloat16 l2 = __float2bfloat16(v.z - __bfloat162float(h2));
    __nv_bfloat16 l3 = __float2bfloat16(v.w - __bfloat162float(h3));
    __nv_bfloat162 H01; H01.x = h0; H01.y = h1;
    __nv_bfloat162 H23; H23.x = h2; H23.y = h3;
    __nv_bfloat162 L01; L01.x = l0; L01.y = l1;
    __nv_bfloat162 L23; L23.x = l2; L23.y = l3;
    h.x = *reinterpret_cast<uint32_t*>(&H01);
    h.y = *reinterpret_cast<uint32_t*>(&H23);
    l.x = *reinterpret_cast<uint32_t*>(&L01);
    l.y = *reinterpret_cast<uint32_t*>(&L23);
}

__device__ __forceinline__ void mma_bf16(float* d, const uint32_t* a, const uint32_t* b) {
    asm volatile(
        "mma.sync.aligned.m16n8k16.row.col.f32.bf16.bf16.f32 "
        "{%0,%1,%2,%3},{%4,%5,%6,%7},{%8,%9},{%0,%1,%2,%3};"
        : "+f"(d[0]), "+f"(d[1]), "+f"(d[2]), "+f"(d[3])
        : "r"(a[0]), "r"(a[1]), "r"(a[2]), "r"(a[3]), "r"(b[0]), "r"(b[1]));
}

// C[M,N] = A[M,K] * B[N,K]^T (NT). A fp32; B fp32 OR preconverted bf16 hi/lo.
// fp32 operands split to bf16 hi/lo on the fly; acc = AhBh + AhBl + AlBh in fp32.
template <bool TANH, bool BBF16>
__global__ __launch_bounds__(NTH, 2)
void gemm_mma(const float* __restrict__ A, const float* __restrict__ Bf,
              const __nv_bfloat16* __restrict__ Bh, const __nv_bfloat16* __restrict__ Bl,
              float* __restrict__ C, int M, int N, int K,
              long sA, long sB, long sC)
{
    extern __shared__ char sm[];

    const int tid = threadIdx.x;
    const int wid = tid >> 5;
    const int lane = tid & 31;
    const int g = lane >> 2;       // 0..7
    const int q = lane & 3;        // 0..3
    const int warpM = (wid & 3) * 32;   // 0,32,64,96
    const int warpN = (wid >> 2) * 64;  // 0,64

    const int bz = blockIdx.z;
    A += (long)bz * sA;
    if (BBF16) { Bh += (long)bz * sB; Bl += (long)bz * sB; }
    else       { Bf += (long)bz * sB; }
    C += (long)bz * sC;

    const int rowBlk = blockIdx.y * BM;
    const int colBlk = blockIdx.x * BN;

    float acc[2][8][4];
#pragma unroll
    for (int mt = 0; mt < 2; mt++)
#pragma unroll
        for (int nt = 0; nt < 8; nt++)
#pragma unroll
            for (int j = 0; j < 4; j++) acc[mt][nt][j] = 0.0f;

    const int S = K / BK;

    float4 ar[4];
    float4 br[4];
    uint4  bb[4];

    // ---- prologue: load + stage stage 0 ----
#pragma unroll
    for (int i = 0; i < 4; i++) {
        int slot = tid + i * NTH;              // 1024 slots: 128 rows x 8 float4
        int r = slot >> 3, c4 = (slot & 7) << 2;
        ar[i] = *reinterpret_cast<const float4*>(A + (long)(rowBlk + r) * K + c4);
    }
    if (!BBF16) {
#pragma unroll
        for (int i = 0; i < 4; i++) {
            int slot = tid + i * NTH;
            int r = slot >> 3, c4 = (slot & 7) << 2;
            br[i] = *reinterpret_cast<const float4*>(Bf + (long)(colBlk + r) * K + c4);
        }
    } else {
#pragma unroll
        for (int i = 0; i < 4; i++) {
            int slot = tid + i * NTH;          // 1024 slots: hi(512) + lo(512)
            int hl = slot >> 9, s2 = slot & 511;
            int r = s2 >> 2, k8 = (s2 & 3) << 3;
            const __nv_bfloat16* src = hl ? Bl : Bh;
            bb[i] = *reinterpret_cast<const uint4*>(src + (long)(colBlk + r) * K + k8);
        }
    }
    {
        char* st = sm;   // buffer 0
#pragma unroll
        for (int i = 0; i < 4; i++) {
            int slot = tid + i * NTH;
            int r = slot >> 3, c4 = (slot & 7) << 2;
            uint2 h, l; split4(ar[i], h, l);
            *reinterpret_cast<uint2*>(st + A_HI + r * ROWB + c4 * 2) = h;
            *reinterpret_cast<uint2*>(st + A_LO + r * ROWB + c4 * 2) = l;
        }
        if (!BBF16) {
#pragma unroll
            for (int i = 0; i < 4; i++) {
                int slot = tid + i * NTH;
                int r = slot >> 3, c4 = (slot & 7) << 2;
                uint2 h, l; split4(br[i], h, l);
                *reinterpret_cast<uint2*>(st + B_HI + r * ROWB + c4 * 2) = h;
                *reinterpret_cast<uint2*>(st + B_LO + r * ROWB + c4 * 2) = l;
            }
        } else {
#pragma unroll
            for (int i = 0; i < 4; i++) {
                int slot = tid + i * NTH;
                int hl = slot >> 9, s2 = slot & 511;
                int r = s2 >> 2, k8 = (s2 & 3) << 3;
                *reinterpret_cast<uint4*>(st + (hl ? B_LO : B_HI) + r * ROWB + k8 * 2) = bb[i];
            }
        }
    }
    __syncthreads();

    for (int s = 0; s < S; s++) {
        // prefetch next stage into registers
        if (s + 1 < S) {
            const int k0 = (s + 1) * BK;
#pragma unroll
            for (int i = 0; i < 4; i++) {
                int slot = tid + i * NTH;
                int r = slot >> 3, c4 = (slot & 7) << 2;
                ar[i] = *reinterpret_cast<const float4*>(A + (long)(rowBlk + r) * K + k0 + c4);
            }
            if (!BBF16) {
#pragma unroll
                for (int i = 0; i < 4; i++) {
                    int slot = tid + i * NTH;
                    int r = slot >> 3, c4 = (slot & 7) << 2;
                    br[i] = *reinterpret_cast<const float4*>(Bf + (long)(colBlk + r) * K + k0 + c4);
                }
            } else {
#pragma unroll
                for (int i = 0; i < 4; i++) {
                    int slot = tid + i * NTH;
                    int hl = slot >> 9, s2 = slot & 511;
                    int r = s2 >> 2, k8 = (s2 & 3) << 3;
                    const __nv_bfloat16* src = hl ? Bl : Bh;
                    bb[i] = *reinterpret_cast<const uint4*>(src + (long)(colBlk + r) * K + k0 + k8);
                }
            }
        }

        // compute on buffer s&1
        {
            const char* cb = sm + (s & 1) * STAGE;
#pragma unroll
            for (int kk = 0; kk < 2; kk++) {
                const int kb = kk * 32 + q * 4;   // byte offset of k = kk*16 + q*2 (bf16)
                uint32_t ah[2][4], al[2][4];
#pragma unroll
                for (int mt = 0; mt < 2; mt++) {
                    int m = warpM + mt * 16 + g;
                    const char* pa = cb + m * ROWB + kb;
                    ah[mt][0] = *reinterpret_cast<const uint32_t*>(pa + A_HI);
                    ah[mt][1] = *reinterpret_cast<const uint32_t*>(pa + A_HI + 8 * ROWB);
                    ah[mt][2] = *reinterpret_cast<const uint32_t*>(pa + A_HI + 16);
                    ah[mt][3] = *reinterpret_cast<const uint32_t*>(pa + A_HI + 8 * ROWB + 16);
                    al[mt][0] = *reinterpret_cast<const uint32_t*>(pa + A_LO);
                    al[mt][1] = *reinterpret_cast<const uint32_t*>(pa + A_LO + 8 * ROWB);
                    al[mt][2] = *reinterpret_cast<const uint32_t*>(pa + A_LO + 16);
                    al[mt][3] = *reinterpret_cast<const uint32_t*>(pa + A_LO + 8 * ROWB + 16);
                }
#pragma unroll
                for (int nt = 0; nt < 8; nt++) {
                    int n = warpN + nt * 8 + g;
                    const char* pb = cb + n * ROWB + kb;
                    uint32_t bh[2], bl[2];
                    bh[0] = *reinterpret_cast<const uint32_t*>(pb + B_HI);
                    bh[1] = *reinterpret_cast<const uint32_t*>(pb + B_HI + 16);
                    bl[0] = *reinterpret_cast<const uint32_t*>(pb + B_LO);
                    bl[1] = *reinterpret_cast<const uint32_t*>(pb + B_LO + 16);
#pragma unroll
                    for (int mt = 0; mt < 2; mt++) {
                        mma_bf16(acc[mt][nt], ah[mt], bh);
                        mma_bf16(acc[mt][nt], ah[mt], bl);
                        mma_bf16(acc[mt][nt], al[mt], bh);
                    }
                }
            }
        }
        __syncthreads();

        // stage next
        if (s + 1 < S) {
            char* st = sm + ((s + 1) & 1) * STAGE;
#pragma unroll
            for (int i = 0; i < 4; i++) {
                int slot = tid + i * NTH;
                int r = slot >> 3, c4 = (slot & 7) << 2;
                uint2 h, l; split4(ar[i], h, l);
                *reinterpret_cast<uint2*>(st + A_HI + r * ROWB + c4 * 2) = h;
                *reinterpret_cast<uint2*>(st + A_LO + r * ROWB + c4 * 2) = l;
            }
            if (!BBF16) {
#pragma unroll
                for (int i = 0; i < 4; i++) {
                    int slot = tid + i * NTH;
                    int r = slot >> 3, c4 = (slot & 7) << 2;
                    uint2 h, l; split4(br[i], h, l);
                    *reinterpret_cast<uint2*>(st + B_HI + r * ROWB + c4 * 2) = h;
                    *reinterpret_cast<uint2*>(st + B_LO + r * ROWB + c4 * 2) = l;
                }
            } else {
#pragma unroll
                for (int i = 0; i < 4; i++) {
                    int slot = tid + i * NTH;
                    int hl = slot >> 9, s2 = slot & 511;
                    int r = s2 >> 2, k8 = (s2 & 3) << 3;
                    *reinterpret_cast<uint4*>(st + (hl ? B_LO : B_HI) + r * ROWB + k8 * 2) = bb[i];
                }
            }
            __syncthreads();
        }
    }

    // ---- epilogue ----
#pragma unroll
    for (int mt = 0; mt < 2; mt++) {
        const long r0 = rowBlk + warpM + mt * 16 + g;
#pragma unroll
        for (int nt = 0; nt < 8; nt++) {
            const long c = colBlk + warpN + nt * 8 + q * 2;
            float d0 = acc[mt][nt][0], d1 = acc[mt][nt][1];
            float d2 = acc[mt][nt][2], d3 = acc[mt][nt][3];
            if (TANH) { d0 = tanhf(d0); d1 = tanhf(d1); d2 = tanhf(d2); d3 = tanhf(d3); }
            float2 u; u.x = d0; u.y = d1;
            float2 w; w.x = d2; w.y = d3;
            *reinterpret_cast<float2*>(C + r0 * N + c) = u;
            *reinterpret_cast<float2*>(C + (r0 + 8) * N + c) = w;
        }
    }
}

// ---------------- V transpose + bf16 hi/lo split ----------------
__global__ __launch_bounds__(256) void vtrans_kernel(
    const float* __restrict__ V,
    __nv_bfloat16* __restrict__ Vh, __nv_bfloat16* __restrict__ Vl)
{
    __shared__ float t[32][33];
    const int b = blockIdx.z;
    const float* Vb = V + (long)b * LK * DM;
    const int k0 = blockIdx.x * 32, n0 = blockIdx.y * 32;
    const int tx = threadIdx.x & 31, ty = threadIdx.x >> 5;
#pragma unroll
    for (int i = 0; i < 4; i++)
        t[ty + i * 8][tx] = Vb[(long)(k0 + ty + i * 8) * DM + n0 + tx];
    __syncthreads();
    const long obase = (long)b * DM * LK;
#pragma unroll
    for (int i = 0; i < 4; i++) {
        int n = n0 + ty + i * 8, k = k0 + tx;
        float x = t[tx][ty + i * 8];
        __nv_bfloat16 h = __float2bfloat16(x);
        __nv_bfloat16 l = __float2bfloat16(x - __bfloat162float(h));
        Vh[obase + (long)n * LK + k] = h;
        Vl[obase + (long)n * LK + k] = l;
    }
}

// ---------------- softmax ----------------
__global__ __launch_bounds__(256) void softmax_kernel(
    float* __restrict__ att, const int* __restrict__ kli)
{
    const int row = blockIdx.x;
    const int b = row >> 11;
    float* p = att + (long)row * LK;
    const int* m = kli + (long)b * LK;
    const int tid = threadIdx.x;
    const float scale = 0.03125f;

    float vals[8];
    float mx = -3.0e38f;
#pragma unroll
    for (int i = 0; i < 8; i++) {
        int c = tid + i * 256;
        float s = p[c] * scale;
        if (m[c] == 0) s = -1.0e9f;
        vals[i] = s;
        mx = fmaxf(mx, s);
    }

    __shared__ float red[8];
#pragma unroll
    for (int o = 16; o > 0; o >>= 1)
        mx = fmaxf(mx, __shfl_xor_sync(0xffffffffu, mx, o));
    if ((tid & 31) == 0) red[tid >> 5] = mx;
    __syncthreads();
    mx = red[0];
#pragma unroll
    for (int i = 1; i < 8; i++) mx = fmaxf(mx, red[i]);
    __syncthreads();

    float sum = 0.0f;
#pragma unroll
    for (int i = 0; i < 8; i++) {
        vals[i] = expf(vals[i] - mx);
        sum += vals[i];
    }
#pragma unroll
    for (int o = 16; o > 0; o >>= 1)
        sum += __shfl_xor_sync(0xffffffffu, sum, o);
    if ((tid & 31) == 0) red[tid >> 5] = sum;
    __syncthreads();
    sum = 0.0f;
#pragma unroll
    for (int i = 0; i < 8; i++) sum += red[i];

    const float inv = 1.0f / sum;
#pragma unroll
    for (int i = 0; i < 8; i++)
        p[tid + i * 256] = vals[i] * inv;
}

// ---------------- launch ----------------
extern "C" void kernel_launch(void* const* d_in, const int* in_sizes, int n_in,
                              void* d_out, int out_size)
{
    const float* q   = (const float*)d_in[0];   // [B, Lq, Dq]
    const float* k   = (const float*)d_in[1];   // [B, Lk, Dk]
    const float* v   = (const float*)d_in[2];   // [B, Lk, Dv]
    const int*   kli = (const int*)  d_in[3];   // [B, Lk]
    const float* W   = (const float*)d_in[4];   // [Dq, Dk]

    float* out = (float*)d_out;                            // [B, Lq, Dv]
    float* att = out + (size_t)BATCH * LQ * DM;            // [B, Lq, Lk]

    float* kt = nullptr;
    cudaGetSymbolAddress((void**)&kt, g_kt);
    __nv_bfloat16* vth = nullptr;
    __nv_bfloat16* vtl = nullptr;
    cudaGetSymbolAddress((void**)&vth, g_vth);
    cudaGetSymbolAddress((void**)&vtl, g_vtl);

    cudaFuncSetAttribute(gemm_mma<true,  false>, cudaFuncAttributeMaxDynamicSharedMemorySize, DYN_SMEM);
    cudaFuncSetAttribute(gemm_mma<false, false>, cudaFuncAttributeMaxDynamicSharedMemorySize, DYN_SMEM);
    cudaFuncSetAttribute(gemm_mma<false, true >, cudaFuncAttributeMaxDynamicSharedMemorySize, DYN_SMEM);

    // 0) V^T bf16 hi/lo for GEMM3
    vtrans_kernel<<<dim3(LK / 32, DM / 32, BATCH), 256>>>(v, vth, vtl);

    // 1) kt = tanh(K @ W^T): M=Lk, N=Dq, K=Dk (W shared across batch)
    gemm_mma<true, false><<<dim3(DM / BN, LK / BM, BATCH), NTH, DYN_SMEM>>>(
        k, W, nullptr, nullptr, kt, LK, DM, DM,
        (long)LK * DM, 0L, (long)LK * DM);

    // 2) scores = Q @ kt^T: M=Lq, N=Lk, K=Dq
    gemm_mma<false, false><<<dim3(LK / BN, LQ / BM, BATCH), NTH, DYN_SMEM>>>(
        q, kt, nullptr, nullptr, att, LQ, LK, DM,
        (long)LQ * DM, (long)LK * DM, (long)LQ * LK);

    // 3) softmax (scale + mask) in place
    softmax_kernel<<<BATCH * LQ, 256>>>(att, kli);

    // 4) out = att @ V = att @ (V^T)^T: M=Lq, N=Dv, K=Lk, B preconverted bf16
    gemm_mma<false, true><<<dim3(DM / BN, LQ / BM, BATCH), NTH, DYN_SMEM>>>(
        att, nullptr, vth, vtl, out, LQ, DM, LK,
        (long)LQ * LK, (long)DM * LK, (long)LQ * DM);
}

// round 6
// speedup vs baseline: 2.5755x; 1.1427x over previous
#include <cuda_runtime.h>
#include <cuda_bf16.h>
#include <math.h>
#include <stdint.h>

// Problem shape (fixed): B=16, Lq=Lk=2048, Dq=Dk=Dv=1024
#define BATCH 16
#define LQ 2048
#define LK 2048
#define DM 1024

// GEMM tiling
#define BM 128
#define BN 128
#define BK 32
#define NTH 256

// smem: K-major bf16 tiles, 64B data rows padded to 80B (conflict-free for LDSM)
#define ROWB 80
#define TILE_B (128 * ROWB)          // 10240
#define A_HI 0
#define A_LO TILE_B
#define B_HI (2 * TILE_B)
#define B_LO (3 * TILE_B)
#define STAGE (4 * TILE_B)           // 40960
#define DYN_SMEM (2 * STAGE)         // 81920

// ---------------- device scratch (preconverted bf16 hi/lo operands) ----------------
__device__ __nv_bfloat16 g_qh[(size_t)BATCH * LQ * DM];
__device__ __nv_bfloat16 g_ql[(size_t)BATCH * LQ * DM];
__device__ __nv_bfloat16 g_kh[(size_t)BATCH * LK * DM];
__device__ __nv_bfloat16 g_kl[(size_t)BATCH * LK * DM];
__device__ __nv_bfloat16 g_wh[(size_t)DM * DM];
__device__ __nv_bfloat16 g_wl[(size_t)DM * DM];
__device__ __nv_bfloat16 g_kth[(size_t)BATCH * LK * DM];   // split(tanh(K W^T))
__device__ __nv_bfloat16 g_ktl[(size_t)BATCH * LK * DM];
__device__ __nv_bfloat16 g_vth[(size_t)BATCH * DM * LK];   // V^T split
__device__ __nv_bfloat16 g_vtl[(size_t)BATCH * DM * LK];
__device__ __nv_bfloat16 g_ath[(size_t)BATCH * LQ * LK];   // split(att)
__device__ __nv_bfloat16 g_atl[(size_t)BATCH * LQ * LK];

// ---------------- helpers ----------------
__device__ __forceinline__ void split4(float4 v, uint2& h, uint2& l) {
    __nv_bfloat16 h0 = __float2bfloat16(v.x);
    __nv_bfloat16 h1 = __float2bfloat16(v.y);
    __nv_bfloat16 h2 = __float2bfloat16(v.z);
    __nv_bfloat16 h3 = __float2bfloat16(v.w);
    __nv_bfloat16 l0 = __float2bfloat16(v.x - __bfloat162float(h0));
    __nv_bfloat16 l1 = __float2bfloat16(v.y - __bfloat162float(h1));
    __nv_bfloat16 l2 = __float2bfloat16(v.z - __bfloat162float(h2));
    __nv_bfloat16 l3 = __float2bfloat16(v.w - __bfloat162float(h3));
    __nv_bfloat162 H01; H01.x = h0; H01.y = h1;
    __nv_bfloat162 H23; H23.x = h2; H23.y = h3;
    __nv_bfloat162 L01; L01.x = l0; L01.y = l1;
    __nv_bfloat162 L23; L23.x = l2; L23.y = l3;
    h.x = *reinterpret_cast<uint32_t*>(&H01);
    h.y = *reinterpret_cast<uint32_t*>(&H23);
    l.x = *reinterpret_cast<uint32_t*>(&L01);
    l.y = *reinterpret_cast<uint32_t*>(&L23);
}

__device__ __forceinline__ uint32_t pack_hi(float a, float b) {
    __nv_bfloat162 p; p.x = __float2bfloat16(a); p.y = __float2bfloat16(b);
    return *reinterpret_cast<uint32_t*>(&p);
}

__device__ __forceinline__ void mma_bf16(float* d, const uint32_t* a, const uint32_t* b) {
    asm volatile(
        "mma.sync.aligned.m16n8k16.row.col.f32.bf16.bf16.f32 "
        "{%0,%1,%2,%3},{%4,%5,%6,%7},{%8,%9},{%0,%1,%2,%3};"
        : "+f"(d[0]), "+f"(d[1]), "+f"(d[2]), "+f"(d[3])
        : "r"(a[0]), "r"(a[1]), "r"(a[2]), "r"(a[3]), "r"(b[0]), "r"(b[1]));
}

__device__ __forceinline__ void ldsm4(uint32_t* r, uint32_t a) {
    asm volatile("ldmatrix.sync.aligned.m8n8.x4.shared.b16 {%0,%1,%2,%3}, [%4];"
                 : "=r"(r[0]), "=r"(r[1]), "=r"(r[2]), "=r"(r[3]) : "r"(a));
}

__device__ __forceinline__ void cpasync16(uint32_t dst, const void* src) {
    asm volatile("cp.async.cg.shared.global [%0], [%1], 16;" :: "r"(dst), "l"(src));
}
__device__ __forceinline__ void cp_commit() {
    asm volatile("cp.async.commit_group;" ::: "memory");
}
__device__ __forceinline__ void cp_wait1() {
    asm volatile("cp.async.wait_group 1;" ::: "memory");
}
__device__ __forceinline__ void cp_wait0() {
    asm volatile("cp.async.wait_group 0;" ::: "memory");
}

// ---------------- GEMM: C[M,N] = A[M,K] * B[N,K]^T, bf16 hi/lo 3-term ----------------
// EPI=0: write fp32 to Cf.  EPI=1: tanh then split, write Ch/Cl bf16.
template <int EPI>
__global__ __launch_bounds__(NTH, 2)
void gemm_bf(const __nv_bfloat16* __restrict__ Ah, const __nv_bfloat16* __restrict__ Al,
             const __nv_bfloat16* __restrict__ Bh, const __nv_bfloat16* __restrict__ Bl,
             float* __restrict__ Cf,
             __nv_bfloat16* __restrict__ Ch, __nv_bfloat16* __restrict__ Cl,
             int M, int N, int K, long sA, long sB, long sC)
{
    extern __shared__ char sm[];
    const uint32_t usm = (uint32_t)__cvta_generic_to_shared(sm);

    const int tid = threadIdx.x;
    const int wid = tid >> 5;
    const int lane = tid & 31;
    const int g = lane >> 2;
    const int q = lane & 3;
    const int warpM = (wid & 3) * 32;
    const int warpN = (wid >> 2) * 64;

    const int bz = blockIdx.z;
    Ah += (long)bz * sA; Al += (long)bz * sA;
    Bh += (long)bz * sB; Bl += (long)bz * sB;
    if (EPI == 0) Cf += (long)bz * sC;
    else { Ch += (long)bz * sC; Cl += (long)bz * sC; }

    const int rowBlk = blockIdx.y * BM;
    const int colBlk = blockIdx.x * BN;

    float acc[2][8][4];
#pragma unroll
    for (int mt = 0; mt < 2; mt++)
#pragma unroll
        for (int nt = 0; nt < 8; nt++)
#pragma unroll
            for (int j = 0; j < 4; j++) acc[mt][nt][j] = 0.0f;

    // ldmatrix lane addressing
    const int jj = lane >> 3, lr = lane & 7;
    const uint32_t aOff = (uint32_t)((warpM + (jj & 1) * 8 + lr) * ROWB + (jj >> 1) * 16);
    const uint32_t bOff = (uint32_t)((warpN + (jj >> 1) * 8 + lr) * ROWB + (jj & 1) * 16);

    const int S = K / BK;

    // stage loader: 8 cp.async per thread (2048 x 16B chunks)
    auto load_stage = [&](int s, int bufo) {
        const int k0 = s * BK;
#pragma unroll
        for (int i = 0; i < 8; i++) {
            const int comp = i >> 1;
            const int w = tid + (i & 1) * NTH;     // 0..511
            const int r = w >> 2, ch = w & 3;
            const uint32_t dst = usm + bufo + comp * TILE_B + r * ROWB + ch * 16;
            const __nv_bfloat16* src;
            long row;
            if (comp == 0)      { src = Ah; row = rowBlk + r; }
            else if (comp == 1) { src = Al; row = rowBlk + r; }
            else if (comp == 2) { src = Bh; row = colBlk + r; }
            else                { src = Bl; row = colBlk + r; }
            cpasync16(dst, src + row * (long)K + k0 + ch * 8);
        }
    };

    load_stage(0, 0);
    cp_commit();

    for (int s = 0; s < S; s++) {
        if (s + 1 < S) {
            load_stage(s + 1, ((s + 1) & 1) * STAGE);
            cp_commit();
            cp_wait1();
        } else {
            cp_wait0();
        }
        __syncthreads();

        const uint32_t bufo = usm + (s & 1) * STAGE;
#pragma unroll
        for (int kk = 0; kk < 2; kk++) {
            const uint32_t kb = bufo + kk * 32;
            uint32_t ah[2][4], al_[2][4];
            ldsm4(ah[0],  kb + A_HI + aOff);
            ldsm4(ah[1],  kb + A_HI + aOff + 16 * ROWB);
            ldsm4(al_[0], kb + A_LO + aOff);
            ldsm4(al_[1], kb + A_LO + aOff + 16 * ROWB);
#pragma unroll
            for (int half = 0; half < 2; half++) {
                uint32_t bh[8], bl[8];
                ldsm4(bh + 0, kb + B_HI + bOff + (half * 2 + 0) * 16 * ROWB);
                ldsm4(bh + 4, kb + B_HI + bOff + (half * 2 + 1) * 16 * ROWB);
                ldsm4(bl + 0, kb + B_LO + bOff + (half * 2 + 0) * 16 * ROWB);
                ldsm4(bl + 4, kb + B_LO + bOff + (half * 2 + 1) * 16 * ROWB);
#pragma unroll
                for (int n2 = 0; n2 < 4; n2++) {
                    const int nt = half * 4 + n2;
#pragma unroll
                    for (int mt = 0; mt < 2; mt++) {
                        mma_bf16(acc[mt][nt], ah[mt],  bh + n2 * 2);
                        mma_bf16(acc[mt][nt], ah[mt],  bl + n2 * 2);
                        mma_bf16(acc[mt][nt], al_[mt], bh + n2 * 2);
                    }
                }
            }
        }
        __syncthreads();
    }

    // ---- epilogue ----
#pragma unroll
    for (int mt = 0; mt < 2; mt++) {
        const long r0 = rowBlk + warpM + mt * 16 + g;
#pragma unroll
        for (int nt = 0; nt < 8; nt++) {
            const long c = colBlk + warpN + nt * 8 + q * 2;
            float d0 = acc[mt][nt][0], d1 = acc[mt][nt][1];
            float d2 = acc[mt][nt][2], d3 = acc[mt][nt][3];
            if (EPI == 1) {
                d0 = tanhf(d0); d1 = tanhf(d1); d2 = tanhf(d2); d3 = tanhf(d3);
                __nv_bfloat16 h0 = __float2bfloat16(d0), h1 = __float2bfloat16(d1);
                __nv_bfloat16 h2 = __float2bfloat16(d2), h3 = __float2bfloat16(d3);
                __nv_bfloat162 H0; H0.x = h0; H0.y = h1;
                __nv_bfloat162 H2; H2.x = h2; H2.y = h3;
                __nv_bfloat162 L0; L0.x = __float2bfloat16(d0 - __bfloat162float(h0));
                L0.y = __float2bfloat16(d1 - __bfloat162float(h1));
                __nv_bfloat162 L2; L2.x = __float2bfloat16(d2 - __bfloat162float(h2));
                L2.y = __float2bfloat16(d3 - __bfloat162float(h3));
                *reinterpret_cast<uint32_t*>(Ch + r0 * N + c)       = *reinterpret_cast<uint32_t*>(&H0);
                *reinterpret_cast<uint32_t*>(Cl + r0 * N + c)       = *reinterpret_cast<uint32_t*>(&L0);
                *reinterpret_cast<uint32_t*>(Ch + (r0 + 8) * N + c) = *reinterpret_cast<uint32_t*>(&H2);
                *reinterpret_cast<uint32_t*>(Cl + (r0 + 8) * N + c) = *reinterpret_cast<uint32_t*>(&L2);
            } else {
                float2 u; u.x = d0; u.y = d1;
                float2 w; w.x = d2; w.y = d3;
                *reinterpret_cast<float2*>(Cf + r0 * N + c) = u;
                *reinterpret_cast<float2*>(Cf + (r0 + 8) * N + c) = w;
            }
        }
    }
}

// ---------------- elementwise fp32 -> bf16 hi/lo ----------------
__global__ __launch_bounds__(256) void conv_split(
    const float4* __restrict__ x, uint2* __restrict__ h, uint2* __restrict__ l, int n4)
{
    int i = blockIdx.x * blockDim.x + threadIdx.x;
    if (i < n4) {
        uint2 hh, ll;
        split4(x[i], hh, ll);
        h[i] = hh; l[i] = ll;
    }
}

// ---------------- V transpose + split ----------------
__global__ __launch_bounds__(256) void vtrans_kernel(
    const float* __restrict__ V,
    __nv_bfloat16* __restrict__ Vh, __nv_bfloat16* __restrict__ Vl)
{
    __shared__ float t[32][33];
    const int b = blockIdx.z;
    const float* Vb = V + (long)b * LK * DM;
    const int k0 = blockIdx.x * 32, n0 = blockIdx.y * 32;
    const int tx = threadIdx.x & 31, ty = threadIdx.x >> 5;
#pragma unroll
    for (int i = 0; i < 4; i++)
        t[ty + i * 8][tx] = Vb[(long)(k0 + ty + i * 8) * DM + n0 + tx];
    __syncthreads();
    const long obase = (long)b * DM * LK;
#pragma unroll
    for (int i = 0; i < 4; i++) {
        int n = n0 + ty + i * 8, k = k0 + tx;
        float x = t[tx][ty + i * 8];
        __nv_bfloat16 h = __float2bfloat16(x);
        __nv_bfloat16 l = __float2bfloat16(x - __bfloat162float(h));
        Vh[obase + (long)n * LK + k] = h;
        Vl[obase + (long)n * LK + k] = l;
    }
}

// ---------------- softmax: fp32 att out + bf16 hi/lo split out ----------------
__global__ __launch_bounds__(256) void softmax_kernel(
    float* __restrict__ att, const int* __restrict__ kli,
    __nv_bfloat16* __restrict__ ath, __nv_bfloat16* __restrict__ atl)
{
    const int row = blockIdx.x;
    const int b = row >> 11;
    float* p = att + (long)row * LK;
    const int* m = kli + (long)b * LK;
    const int tid = threadIdx.x;
    const int c0 = tid * 8;
    const float scale = 0.03125f;

    float vals[8];
    {
        float4 x0 = *reinterpret_cast<const float4*>(p + c0);
        float4 x1 = *reinterpret_cast<const float4*>(p + c0 + 4);
        int4 m0 = *reinterpret_cast<const int4*>(m + c0);
        int4 m1 = *reinterpret_cast<const int4*>(m + c0 + 4);
        vals[0] = (m0.x == 0) ? -1.0e9f : x0.x * scale;
        vals[1] = (m0.y == 0) ? -1.0e9f : x0.y * scale;
        vals[2] = (m0.z == 0) ? -1.0e9f : x0.z * scale;
        vals[3] = (m0.w == 0) ? -1.0e9f : x0.w * scale;
        vals[4] = (m1.x == 0) ? -1.0e9f : x1.x * scale;
        vals[5] = (m1.y == 0) ? -1.0e9f : x1.y * scale;
        vals[6] = (m1.z == 0) ? -1.0e9f : x1.z * scale;
        vals[7] = (m1.w == 0) ? -1.0e9f : x1.w * scale;
    }

    float mx = vals[0];
#pragma unroll
    for (int i = 1; i < 8; i++) mx = fmaxf(mx, vals[i]);

    __shared__ float red[8];
#pragma unroll
    for (int o = 16; o > 0; o >>= 1)
        mx = fmaxf(mx, __shfl_xor_sync(0xffffffffu, mx, o));
    if ((tid & 31) == 0) red[tid >> 5] = mx;
    __syncthreads();
    mx = red[0];
#pragma unroll
    for (int i = 1; i < 8; i++) mx = fmaxf(mx, red[i]);
    __syncthreads();

    float sum = 0.0f;
#pragma unroll
    for (int i = 0; i < 8; i++) {
        vals[i] = expf(vals[i] - mx);
        sum += vals[i];
    }
#pragma unroll
    for (int o = 16; o > 0; o >>= 1)
        sum += __shfl_xor_sync(0xffffffffu, sum, o);
    if ((tid & 31) == 0) red[tid >> 5] = sum;
    __syncthreads();
    sum = 0.0f;
#pragma unroll
    for (int i = 0; i < 8; i++) sum += red[i];

    const float inv = 1.0f / sum;
#pragma unroll
    for (int i = 0; i < 8; i++) vals[i] *= inv;

    // fp32 out
    float4 y0; y0.x = vals[0]; y0.y = vals[1]; y0.z = vals[2]; y0.w = vals[3];
    float4 y1; y1.x = vals[4]; y1.y = vals[5]; y1.z = vals[6]; y1.w = vals[7];
    *reinterpret_cast<float4*>(p + c0) = y0;
    *reinterpret_cast<float4*>(p + c0 + 4) = y1;

    // bf16 hi/lo out
    uint2 h0, l0, h1, l1;
    split4(y0, h0, l0);
    split4(y1, h1, l1);
    uint4 H; H.x = h0.x; H.y = h0.y; H.z = h1.x; H.w = h1.y;
    uint4 L; L.x = l0.x; L.y = l0.y; L.z = l1.x; L.w = l1.y;
    *reinterpret_cast<uint4*>(ath + (long)row * LK + c0) = H;
    *reinterpret_cast<uint4*>(atl + (long)row * LK + c0) = L;
}

// ---------------- launch ----------------
extern "C" void kernel_launch(void* const* d_in, const int* in_sizes, int n_in,
                              void* d_out, int out_size)
{
    const float* q   = (const float*)d_in[0];   // [B, Lq, Dq]
    const float* k   = (const float*)d_in[1];   // [B, Lk, Dk]
    const float* v   = (const float*)d_in[2];   // [B, Lk, Dv]
    const int*   kli = (const int*)  d_in[3];   // [B, Lk]
    const float* W   = (const float*)d_in[4];   // [Dq, Dk]

    float* out = (float*)d_out;                            // [B, Lq, Dv]
    float* att = out + (size_t)BATCH * LQ * DM;            // [B, Lq, Lk]

    __nv_bfloat16 *qh, *ql, *kh, *kl, *wh, *wl, *kth, *ktl, *vth, *vtl, *ath, *atl;
    cudaGetSymbolAddress((void**)&qh, g_qh);   cudaGetSymbolAddress((void**)&ql, g_ql);
    cudaGetSymbolAddress((void**)&kh, g_kh);   cudaGetSymbolAddress((void**)&kl, g_kl);
    cudaGetSymbolAddress((void**)&wh, g_wh);   cudaGetSymbolAddress((void**)&wl, g_wl);
    cudaGetSymbolAddress((void**)&kth, g_kth); cudaGetSymbolAddress((void**)&ktl, g_ktl);
    cudaGetSymbolAddress((void**)&vth, g_vth); cudaGetSymbolAddress((void**)&vtl, g_vtl);
    cudaGetSymbolAddress((void**)&ath, g_ath); cudaGetSymbolAddress((void**)&atl, g_atl);

    cudaFuncSetAttribute(gemm_bf<0>, cudaFuncAttributeMaxDynamicSharedMemorySize, DYN_SMEM);
    cudaFuncSetAttribute(gemm_bf<1>, cudaFuncAttributeMaxDynamicSharedMemorySize, DYN_SMEM);

    // 0) preconvert operands
    const int nQK4 = BATCH * LQ * DM / 4;
    conv_split<<<nQK4 / 256, 256>>>((const float4*)q, (uint2*)qh, (uint2*)ql, nQK4);
    conv_split<<<nQK4 / 256, 256>>>((const float4*)k, (uint2*)kh, (uint2*)kl, nQK4);
    const int nW4 = DM * DM / 4;
    conv_split<<<nW4 / 256, 256>>>((const float4*)W, (uint2*)wh, (uint2*)wl, nW4);
    vtrans_kernel<<<dim3(LK / 32, DM / 32, BATCH), 256>>>(v, vth, vtl);

    // 1) kt = tanh(K @ W^T), output split bf16. M=Lk, N=Dq, K=Dk. W broadcast.
    gemm_bf<1><<<dim3(DM / BN, LK / BM, BATCH), NTH, DYN_SMEM>>>(
        kh, kl, wh, wl, nullptr, kth, ktl,
        LK, DM, DM, (long)LK * DM, 0L, (long)LK * DM);

    // 2) scores = Q @ kt^T -> att (fp32). M=Lq, N=Lk, K=Dq.
    gemm_bf<0><<<dim3(LK / BN, LQ / BM, BATCH), NTH, DYN_SMEM>>>(
        qh, ql, kth, ktl, att, nullptr, nullptr,
        LQ, LK, DM, (long)LQ * DM, (long)LK * DM, (long)LQ * LK);

    // 3) softmax in place + emit split bf16 att
    softmax_kernel<<<BATCH * LQ, 256>>>(att, kli, ath, atl);

    // 4) out = att @ V. M=Lq, N=Dv, K=Lk.
    gemm_bf<0><<<dim3(DM / BN, LQ / BM, BATCH), NTH, DYN_SMEM>>>(
        ath, atl, vth, vtl, out, nullptr, nullptr,
        LQ, DM, LK, (long)LQ * LK, (long)DM * LK, (long)LQ * DM);
}

// round 7
// speedup vs baseline: 3.6718x; 1.4257x over previous
#include <cuda_runtime.h>
#include <cuda_fp16.h>
#include <math.h>
#include <stdint.h>

// Problem shape (fixed): B=16, Lq=Lk=2048, Dq=Dk=Dv=1024
#define BATCH 16
#define LQ 2048
#define LK 2048
#define DM 1024

// GEMM tiling
#define BM 128
#define BN 128
#define BK 32
#define NTH 256

// smem: K-major fp16 tiles, 64B data rows padded to 80B (conflict-free LDSM)
#define ROWB 80
#define TILE_B (128 * ROWB)          // 10240
#define A_HI 0
#define A_LO TILE_B
#define B_T  (2 * TILE_B)
#define STAGE (3 * TILE_B)           // 30720
#define NSTAGE 3
#define DYN_SMEM (NSTAGE * STAGE)    // 92160

// ---------------- device scratch (preconverted fp16 operands) ----------------
__device__ __half g_qh[(size_t)BATCH * LQ * DM];
__device__ __half g_ql[(size_t)BATCH * LQ * DM];
__device__ __half g_kh[(size_t)BATCH * LK * DM];
__device__ __half g_kl[(size_t)BATCH * LK * DM];
__device__ __half g_wh[(size_t)DM * DM];            // W single fp16
__device__ __half g_kth[(size_t)BATCH * LK * DM];   // tanh(K W^T) single fp16
__device__ __half g_vth[(size_t)BATCH * DM * LK];   // V^T single fp16
__device__ __half g_ath[(size_t)BATCH * LQ * LK];   // att hi
__device__ __half g_atl[(size_t)BATCH * LQ * LK];   // att lo

// ---------------- helpers ----------------
__device__ __forceinline__ void split4h(float4 v, uint2& h, uint2& l) {
    __half h0 = __float2half(v.x), h1 = __float2half(v.y);
    __half h2 = __float2half(v.z), h3 = __float2half(v.w);
    __half l0 = __float2half(v.x - __half2float(h0));
    __half l1 = __float2half(v.y - __half2float(h1));
    __half l2 = __float2half(v.z - __half2float(h2));
    __half l3 = __float2half(v.w - __half2float(h3));
    __half2 H01; H01.x = h0; H01.y = h1;
    __half2 H23; H23.x = h2; H23.y = h3;
    __half2 L01; L01.x = l0; L01.y = l1;
    __half2 L23; L23.x = l2; L23.y = l3;
    h.x = *reinterpret_cast<uint32_t*>(&H01);
    h.y = *reinterpret_cast<uint32_t*>(&H23);
    l.x = *reinterpret_cast<uint32_t*>(&L01);
    l.y = *reinterpret_cast<uint32_t*>(&L23);
}

__device__ __forceinline__ uint2 round4h(float4 v) {
    __half2 H01; H01.x = __float2half(v.x); H01.y = __float2half(v.y);
    __half2 H23; H23.x = __float2half(v.z); H23.y = __float2half(v.w);
    uint2 r;
    r.x = *reinterpret_cast<uint32_t*>(&H01);
    r.y = *reinterpret_cast<uint32_t*>(&H23);
    return r;
}

__device__ __forceinline__ void mma_f16(float* d, const uint32_t* a, const uint32_t* b) {
    asm volatile(
        "mma.sync.aligned.m16n8k16.row.col.f32.f16.f16.f32 "
        "{%0,%1,%2,%3},{%4,%5,%6,%7},{%8,%9},{%0,%1,%2,%3};"
        : "+f"(d[0]), "+f"(d[1]), "+f"(d[2]), "+f"(d[3])
        : "r"(a[0]), "r"(a[1]), "r"(a[2]), "r"(a[3]), "r"(b[0]), "r"(b[1]));
}

__device__ __forceinline__ void ldsm4(uint32_t* r, uint32_t a) {
    asm volatile("ldmatrix.sync.aligned.m8n8.x4.shared.b16 {%0,%1,%2,%3}, [%4];"
                 : "=r"(r[0]), "=r"(r[1]), "=r"(r[2]), "=r"(r[3]) : "r"(a));
}

__device__ __forceinline__ void cpasync16(uint32_t dst, const void* src) {
    asm volatile("cp.async.cg.shared.global [%0], [%1], 16;" :: "r"(dst), "l"(src));
}
__device__ __forceinline__ void cp_commit() {
    asm volatile("cp.async.commit_group;" ::: "memory");
}
__device__ __forceinline__ void cp_wait1() {
    asm volatile("cp.async.wait_group 1;" ::: "memory");
}
__device__ __forceinline__ void cp_wait0() {
    asm volatile("cp.async.wait_group 0;" ::: "memory");
}

// ---------------- GEMM: C[M,N] = (Ah+Al)[M,K] * B[N,K]^T, 2-term fp16 ----------------
// EPI=0: write fp32 to Cf.  EPI=1: tanh then round, write Ch fp16.
template <int EPI>
__global__ __launch_bounds__(NTH, 2)
void gemm_h(const __half* __restrict__ Ah, const __half* __restrict__ Al,
            const __half* __restrict__ Bh,
            float* __restrict__ Cf, __half* __restrict__ Ch,
            int M, int N, int K, long sA, long sB, long sC)
{
    extern __shared__ char sm[];
    const uint32_t usm = (uint32_t)__cvta_generic_to_shared(sm);

    const int tid = threadIdx.x;
    const int wid = tid >> 5;
    const int lane = tid & 31;
    const int g = lane >> 2;
    const int q = lane & 3;
    const int warpM = (wid & 3) * 32;
    const int warpN = (wid >> 2) * 64;

    const int bz = blockIdx.z;
    Ah += (long)bz * sA; Al += (long)bz * sA;
    Bh += (long)bz * sB;
    if (EPI == 0) Cf += (long)bz * sC; else Ch += (long)bz * sC;

    const int rowBlk = blockIdx.y * BM;
    const int colBlk = blockIdx.x * BN;

    float acc[2][8][4];
#pragma unroll
    for (int mt = 0; mt < 2; mt++)
#pragma unroll
        for (int nt = 0; nt < 8; nt++)
#pragma unroll
            for (int j = 0; j < 4; j++) acc[mt][nt][j] = 0.0f;

    // ldmatrix lane addressing
    const int jj = lane >> 3, lr = lane & 7;
    const uint32_t aOff = (uint32_t)((warpM + (jj & 1) * 8 + lr) * ROWB + (jj >> 1) * 16);
    const uint32_t bOff = (uint32_t)((warpN + (jj >> 1) * 8 + lr) * ROWB + (jj & 1) * 16);

    const int S = K / BK;

    // loader: 6 cp.async per thread (1536 x 16B chunks: Ah 512, Al 512, B 512)
    auto load_stage = [&](int s, uint32_t bufo) {
        const int k0 = s * BK;
#pragma unroll
        for (int i = 0; i < 6; i++) {
            const int comp = i >> 1;
            const int w = tid + (i & 1) * NTH;     // 0..511
            const int r = w >> 2, ch = w & 3;
            const uint32_t dst = usm + bufo + comp * TILE_B + r * ROWB + ch * 16;
            const __half* src;
            long row;
            if (comp == 0)      { src = Ah; row = rowBlk + r; }
            else if (comp == 1) { src = Al; row = rowBlk + r; }
            else                { src = Bh; row = colBlk + r; }
            cpasync16(dst, src + row * (long)K + k0 + ch * 8);
        }
    };

    // prologue: stages 0,1
    load_stage(0, 0);
    cp_commit();
    if (S > 1) { load_stage(1, STAGE); }
    cp_commit();

    for (int s = 0; s < S; s++) {
        // wait for stage s (leave at most 1 younger group pending)
        if (s + 1 < S) cp_wait1(); else cp_wait0();
        __syncthreads();   // data visible to all; all warps done with prior compute

        // prefetch stage s+2 into its slot (that slot was consumed at iter s-1,
        // and every warp passed the sync above after finishing it)
        if (s + 2 < S) { load_stage(s + 2, (uint32_t)(((s + 2) % NSTAGE) * STAGE)); }
        cp_commit();

        const uint32_t bufo = usm + (uint32_t)((s % NSTAGE) * STAGE);
#pragma unroll
        for (int kk = 0; kk < 2; kk++) {
            const uint32_t kb = bufo + kk * 32;
            uint32_t ah[2][4], al_[2][4];
            ldsm4(ah[0],  kb + A_HI + aOff);
            ldsm4(ah[1],  kb + A_HI + aOff + 16 * ROWB);
            ldsm4(al_[0], kb + A_LO + aOff);
            ldsm4(al_[1], kb + A_LO + aOff + 16 * ROWB);
#pragma unroll
            for (int half = 0; half < 2; half++) {
                uint32_t bh[8];
                ldsm4(bh + 0, kb + B_T + bOff + (half * 2 + 0) * 16 * ROWB);
                ldsm4(bh + 4, kb + B_T + bOff + (half * 2 + 1) * 16 * ROWB);
#pragma unroll
                for (int n2 = 0; n2 < 4; n2++) {
                    const int nt = half * 4 + n2;
#pragma unroll
                    for (int mt = 0; mt < 2; mt++) {
                        mma_f16(acc[mt][nt], ah[mt],  bh + n2 * 2);
                        mma_f16(acc[mt][nt], al_[mt], bh + n2 * 2);
                    }
                }
            }
        }
    }

    // ---- epilogue ----
#pragma unroll
    for (int mt = 0; mt < 2; mt++) {
        const long r0 = rowBlk + warpM + mt * 16 + g;
#pragma unroll
        for (int nt = 0; nt < 8; nt++) {
            const long c = colBlk + warpN + nt * 8 + q * 2;
            float d0 = acc[mt][nt][0], d1 = acc[mt][nt][1];
            float d2 = acc[mt][nt][2], d3 = acc[mt][nt][3];
            if (EPI == 1) {
                d0 = tanhf(d0); d1 = tanhf(d1); d2 = tanhf(d2); d3 = tanhf(d3);
                __half2 H0; H0.x = __float2half(d0); H0.y = __float2half(d1);
                __half2 H2; H2.x = __float2half(d2); H2.y = __float2half(d3);
                *reinterpret_cast<uint32_t*>(Ch + r0 * N + c)       = *reinterpret_cast<uint32_t*>(&H0);
                *reinterpret_cast<uint32_t*>(Ch + (r0 + 8) * N + c) = *reinterpret_cast<uint32_t*>(&H2);
            } else {
                float2 u; u.x = d0; u.y = d1;
                float2 w; w.x = d2; w.y = d3;
                *reinterpret_cast<float2*>(Cf + r0 * N + c) = u;
                *reinterpret_cast<float2*>(Cf + (r0 + 8) * N + c) = w;
            }
        }
    }
}

// ---------------- elementwise fp32 -> fp16 hi/lo ----------------
__global__ __launch_bounds__(256) void conv_split_h(
    const float4* __restrict__ x, uint2* __restrict__ h, uint2* __restrict__ l, int n4)
{
    int i = blockIdx.x * blockDim.x + threadIdx.x;
    if (i < n4) {
        uint2 hh, ll;
        split4h(x[i], hh, ll);
        h[i] = hh; l[i] = ll;
    }
}

// ---------------- elementwise fp32 -> fp16 single ----------------
__global__ __launch_bounds__(256) void conv_round_h(
    const float4* __restrict__ x, uint2* __restrict__ h, int n4)
{
    int i = blockIdx.x * blockDim.x + threadIdx.x;
    if (i < n4) h[i] = round4h(x[i]);
}

// ---------------- V transpose + fp16 round ----------------
__global__ __launch_bounds__(256) void vtrans_kernel(
    const float* __restrict__ V, __half* __restrict__ Vh)
{
    __shared__ float t[32][33];
    const int b = blockIdx.z;
    const float* Vb = V + (long)b * LK * DM;
    const int k0 = blockIdx.x * 32, n0 = blockIdx.y * 32;
    const int tx = threadIdx.x & 31, ty = threadIdx.x >> 5;
#pragma unroll
    for (int i = 0; i < 4; i++)
        t[ty + i * 8][tx] = Vb[(long)(k0 + ty + i * 8) * DM + n0 + tx];
    __syncthreads();
    const long obase = (long)b * DM * LK;
#pragma unroll
    for (int i = 0; i < 4; i++) {
        int n = n0 + ty + i * 8, k = k0 + tx;
        Vh[obase + (long)n * LK + k] = __float2half(t[tx][ty + i * 8]);
    }
}

// ---------------- softmax: fp32 att out + fp16 hi/lo out ----------------
__global__ __launch_bounds__(256) void softmax_kernel(
    float* __restrict__ att, const int* __restrict__ kli,
    __half* __restrict__ ath, __half* __restrict__ atl)
{
    const int row = blockIdx.x;
    const int b = row >> 11;
    float* p = att + (long)row * LK;
    const int* m = kli + (long)b * LK;
    const int tid = threadIdx.x;
    const int c0 = tid * 8;
    const float scale = 0.03125f;

    float vals[8];
    {
        float4 x0 = *reinterpret_cast<const float4*>(p + c0);
        float4 x1 = *reinterpret_cast<const float4*>(p + c0 + 4);
        int4 m0 = *reinterpret_cast<const int4*>(m + c0);
        int4 m1 = *reinterpret_cast<const int4*>(m + c0 + 4);
        vals[0] = (m0.x == 0) ? -1.0e9f : x0.x * scale;
        vals[1] = (m0.y == 0) ? -1.0e9f : x0.y * scale;
        vals[2] = (m0.z == 0) ? -1.0e9f : x0.z * scale;
        vals[3] = (m0.w == 0) ? -1.0e9f : x0.w * scale;
        vals[4] = (m1.x == 0) ? -1.0e9f : x1.x * scale;
        vals[5] = (m1.y == 0) ? -1.0e9f : x1.y * scale;
        vals[6] = (m1.z == 0) ? -1.0e9f : x1.z * scale;
        vals[7] = (m1.w == 0) ? -1.0e9f : x1.w * scale;
    }

    float mx = vals[0];
#pragma unroll
    for (int i = 1; i < 8; i++) mx = fmaxf(mx, vals[i]);

    __shared__ float red[8];
#pragma unroll
    for (int o = 16; o > 0; o >>= 1)
        mx = fmaxf(mx, __shfl_xor_sync(0xffffffffu, mx, o));
    if ((tid & 31) == 0) red[tid >> 5] = mx;
    __syncthreads();
    mx = red[0];
#pragma unroll
    for (int i = 1; i < 8; i++) mx = fmaxf(mx, red[i]);
    __syncthreads();

    float sum = 0.0f;
#pragma unroll
    for (int i = 0; i < 8; i++) {
        vals[i] = expf(vals[i] - mx);
        sum += vals[i];
    }
#pragma unroll
    for (int o = 16; o > 0; o >>= 1)
        sum += __shfl_xor_sync(0xffffffffu, sum, o);
    if ((tid & 31) == 0) red[tid >> 5] = sum;
    __syncthreads();
    sum = 0.0f;
#pragma unroll
    for (int i = 0; i < 8; i++) sum += red[i];

    const float inv = 1.0f / sum;
#pragma unroll
    for (int i = 0; i < 8; i++) vals[i] *= inv;

    float4 y0; y0.x = vals[0]; y0.y = vals[1]; y0.z = vals[2]; y0.w = vals[3];
    float4 y1; y1.x = vals[4]; y1.y = vals[5]; y1.z = vals[6]; y1.w = vals[7];
    *reinterpret_cast<float4*>(p + c0) = y0;
    *reinterpret_cast<float4*>(p + c0 + 4) = y1;

    uint2 h0, l0, h1, l1;
    split4h(y0, h0, l0);
    split4h(y1, h1, l1);
    uint4 H; H.x = h0.x; H.y = h0.y; H.z = h1.x; H.w = h1.y;
    uint4 L; L.x = l0.x; L.y = l0.y; L.z = l1.x; L.w = l1.y;
    *reinterpret_cast<uint4*>(ath + (long)row * LK + c0) = H;
    *reinterpret_cast<uint4*>(atl + (long)row * LK + c0) = L;
}

// ---------------- launch ----------------
extern "C" void kernel_launch(void* const* d_in, const int* in_sizes, int n_in,
                              void* d_out, int out_size)
{
    const float* q   = (const float*)d_in[0];   // [B, Lq, Dq]
    const float* k   = (const float*)d_in[1];   // [B, Lk, Dk]
    const float* v   = (const float*)d_in[2];   // [B, Lk, Dv]
    const int*   kli = (const int*)  d_in[3];   // [B, Lk]
    const float* W   = (const float*)d_in[4];   // [Dq, Dk]

    float* out = (float*)d_out;                            // [B, Lq, Dv]
    float* att = out + (size_t)BATCH * LQ * DM;            // [B, Lq, Lk]

    __half *qh, *ql, *kh, *kl, *wh, *kth, *vth, *ath, *atl;
    cudaGetSymbolAddress((void**)&qh, g_qh);   cudaGetSymbolAddress((void**)&ql, g_ql);
    cudaGetSymbolAddress((void**)&kh, g_kh);   cudaGetSymbolAddress((void**)&kl, g_kl);
    cudaGetSymbolAddress((void**)&wh, g_wh);
    cudaGetSymbolAddress((void**)&kth, g_kth);
    cudaGetSymbolAddress((void**)&vth, g_vth);
    cudaGetSymbolAddress((void**)&ath, g_ath); cudaGetSymbolAddress((void**)&atl, g_atl);

    cudaFuncSetAttribute(gemm_h<0>, cudaFuncAttributeMaxDynamicSharedMemorySize, DYN_SMEM);
    cudaFuncSetAttribute(gemm_h<1>, cudaFuncAttributeMaxDynamicSharedMemorySize, DYN_SMEM);

    // 0) preconvert operands
    const int nQK4 = BATCH * LQ * DM / 4;
    conv_split_h<<<nQK4 / 256, 256>>>((const float4*)q, (uint2*)qh, (uint2*)ql, nQK4);
    conv_split_h<<<nQK4 / 256, 256>>>((const float4*)k, (uint2*)kh, (uint2*)kl, nQK4);
    const int nW4 = DM * DM / 4;
    conv_round_h<<<nW4 / 256, 256>>>((const float4*)W, (uint2*)wh, nW4);
    vtrans_kernel<<<dim3(LK / 32, DM / 32, BATCH), 256>>>(v, vth);

    // 1) kt = tanh(K @ W^T) -> fp16. M=Lk, N=Dq, K=Dk. W broadcast.
    gemm_h<1><<<dim3(DM / BN, LK / BM, BATCH), NTH, DYN_SMEM>>>(
        kh, kl, wh, nullptr, kth,
        LK, DM, DM, (long)LK * DM, 0L, (long)LK * DM);

    // 2) scores = Q @ kt^T -> att (fp32). M=Lq, N=Lk, K=Dq.
    gemm_h<0><<<dim3(LK / BN, LQ / BM, BATCH), NTH, DYN_SMEM>>>(
        qh, ql, kth, att, nullptr,
        LQ, LK, DM, (long)LQ * DM, (long)LK * DM, (long)LQ * LK);

    // 3) softmax in place + emit fp16 hi/lo att
    softmax_kernel<<<BATCH * LQ, 256>>>(att, kli, ath, atl);

    // 4) out = att @ V. M=Lq, N=Dv, K=Lk.
    gemm_h<0><<<dim3(DM / BN, LQ / BM, BATCH), NTH, DYN_SMEM>>>(
        ath, atl, vth, out, nullptr,
        LQ, DM, LK, (long)LQ * LK, (long)DM * LK, (long)LQ * DM);
}

// round 8
// speedup vs baseline: 4.7474x; 1.2929x over previous
#include <cuda_runtime.h>
#include <cuda_fp16.h>
#include <math.h>
#include <stdint.h>

// Problem shape (fixed): B=16, Lq=Lk=2048, Dq=Dk=Dv=1024
#define BATCH 16
#define LQ 2048
#define LK 2048
#define DM 1024

// GEMM tiling
#define BM 128
#define BN 128
#define BK 32
#define NTH 256

// smem: K-major fp16 tiles, 64B data rows padded to 80B (conflict-free LDSM)
#define ROWB 80
#define TILE_B (128 * ROWB)          // 10240
#define NSTAGE 3

// ---------------- device scratch (preconverted fp16 operands) ----------------
__device__ __half g_qh[(size_t)BATCH * LQ * DM];
__device__ __half g_ql[(size_t)BATCH * LQ * DM];
__device__ __half g_kh[(size_t)BATCH * LK * DM];    // K single fp16
__device__ __half g_wh[(size_t)DM * DM];            // W single fp16
__device__ __half g_kth[(size_t)BATCH * LK * DM];   // tanh(K W^T) single fp16
__device__ __half g_vth[(size_t)BATCH * DM * LK];   // V^T single fp16
__device__ __half g_ath[(size_t)BATCH * LQ * LK];   // att single fp16

// ---------------- helpers ----------------
__device__ __forceinline__ void split4h(float4 v, uint2& h, uint2& l) {
    __half h0 = __float2half(v.x), h1 = __float2half(v.y);
    __half h2 = __float2half(v.z), h3 = __float2half(v.w);
    __half l0 = __float2half(v.x - __half2float(h0));
    __half l1 = __float2half(v.y - __half2float(h1));
    __half l2 = __float2half(v.z - __half2float(h2));
    __half l3 = __float2half(v.w - __half2float(h3));
    __half2 H01; H01.x = h0; H01.y = h1;
    __half2 H23; H23.x = h2; H23.y = h3;
    __half2 L01; L01.x = l0; L01.y = l1;
    __half2 L23; L23.x = l2; L23.y = l3;
    h.x = *reinterpret_cast<uint32_t*>(&H01);
    h.y = *reinterpret_cast<uint32_t*>(&H23);
    l.x = *reinterpret_cast<uint32_t*>(&L01);
    l.y = *reinterpret_cast<uint32_t*>(&L23);
}

__device__ __forceinline__ uint2 round4h(float4 v) {
    __half2 H01; H01.x = __float2half(v.x); H01.y = __float2half(v.y);
    __half2 H23; H23.x = __float2half(v.z); H23.y = __float2half(v.w);
    uint2 r;
    r.x = *reinterpret_cast<uint32_t*>(&H01);
    r.y = *reinterpret_cast<uint32_t*>(&H23);
    return r;
}

__device__ __forceinline__ void mma_f16(float* d, const uint32_t* a, const uint32_t* b) {
    asm volatile(
        "mma.sync.aligned.m16n8k16.row.col.f32.f16.f16.f32 "
        "{%0,%1,%2,%3},{%4,%5,%6,%7},{%8,%9},{%0,%1,%2,%3};"
        : "+f"(d[0]), "+f"(d[1]), "+f"(d[2]), "+f"(d[3])
        : "r"(a[0]), "r"(a[1]), "r"(a[2]), "r"(a[3]), "r"(b[0]), "r"(b[1]));
}

__device__ __forceinline__ void ldsm4(uint32_t* r, uint32_t a) {
    asm volatile("ldmatrix.sync.aligned.m8n8.x4.shared.b16 {%0,%1,%2,%3}, [%4];"
                 : "=r"(r[0]), "=r"(r[1]), "=r"(r[2]), "=r"(r[3]) : "r"(a));
}

__device__ __forceinline__ void cpasync16(uint32_t dst, const void* src) {
    asm volatile("cp.async.cg.shared.global [%0], [%1], 16;" :: "r"(dst), "l"(src));
}
__device__ __forceinline__ void cp_commit() {
    asm volatile("cp.async.commit_group;" ::: "memory");
}
__device__ __forceinline__ void cp_wait1() {
    asm volatile("cp.async.wait_group 1;" ::: "memory");
}
__device__ __forceinline__ void cp_wait0() {
    asm volatile("cp.async.wait_group 0;" ::: "memory");
}

// ------------- GEMM: C[M,N] = (Ah[+Al])[M,K] * B[N,K]^T, fp16 HMMA -------------
// ATERMS: 1 or 2 A-side fp16 terms.  EPI=0: fp32 out.  EPI=1: tanh -> fp16 out.
template <int EPI, int ATERMS>
__global__ __launch_bounds__(NTH, 2)
void gemm_h(const __half* __restrict__ Ah, const __half* __restrict__ Al,
            const __half* __restrict__ Bh,
            float* __restrict__ Cf, __half* __restrict__ Ch,
            int M, int N, int K, long sA, long sB, long sC)
{
    constexpr uint32_t A_HI = 0;
    constexpr uint32_t A_LO = TILE_B;                 // only if ATERMS==2
    constexpr uint32_t B_T  = ATERMS * TILE_B;
    constexpr uint32_t STAGE_SZ = (ATERMS + 1) * TILE_B;

    extern __shared__ char sm[];
    const uint32_t usm = (uint32_t)__cvta_generic_to_shared(sm);

    const int tid = threadIdx.x;
    const int wid = tid >> 5;
    const int lane = tid & 31;
    const int g = lane >> 2;
    const int q = lane & 3;
    const int warpM = (wid & 3) * 32;
    const int warpN = (wid >> 2) * 64;

    const int bz = blockIdx.z;
    Ah += (long)bz * sA;
    if (ATERMS == 2) Al += (long)bz * sA;
    Bh += (long)bz * sB;
    if (EPI == 0) Cf += (long)bz * sC; else Ch += (long)bz * sC;

    const int rowBlk = blockIdx.y * BM;
    const int colBlk = blockIdx.x * BN;

    float acc[2][8][4];
#pragma unroll
    for (int mt = 0; mt < 2; mt++)
#pragma unroll
        for (int nt = 0; nt < 8; nt++)
#pragma unroll
            for (int j = 0; j < 4; j++) acc[mt][nt][j] = 0.0f;

    // ldmatrix lane addressing
    const int jj = lane >> 3, lr = lane & 7;
    const uint32_t aOff = (uint32_t)((warpM + (jj & 1) * 8 + lr) * ROWB + (jj >> 1) * 16);
    const uint32_t bOff = (uint32_t)((warpN + (jj >> 1) * 8 + lr) * ROWB + (jj & 1) * 16);

    const int S = K / BK;

    // loader: 2*(ATERMS+1) cp.async per thread
    auto load_stage = [&](int s, uint32_t bufo) {
        const int k0 = s * BK;
#pragma unroll
        for (int i = 0; i < 2 * (ATERMS + 1); i++) {
            const int comp = i >> 1;
            const int w = tid + (i & 1) * NTH;     // 0..511
            const int r = w >> 2, ch = w & 3;
            const uint32_t dst = usm + bufo + comp * TILE_B + r * ROWB + ch * 16;
            const __half* src;
            long row;
            if (comp < ATERMS) { src = (comp == 0) ? Ah : Al; row = rowBlk + r; }
            else               { src = Bh; row = colBlk + r; }
            cpasync16(dst, src + row * (long)K + k0 + ch * 8);
        }
    };

    // prologue: stages 0,1
    load_stage(0, 0);
    cp_commit();
    if (S > 1) { load_stage(1, STAGE_SZ); }
    cp_commit();

    for (int s = 0; s < S; s++) {
        if (s + 1 < S) cp_wait1(); else cp_wait0();
        __syncthreads();

        if (s + 2 < S) { load_stage(s + 2, (uint32_t)(((s + 2) % NSTAGE) * STAGE_SZ)); }
        cp_commit();

        const uint32_t bufo = usm + (uint32_t)((s % NSTAGE) * STAGE_SZ);
#pragma unroll
        for (int kk = 0; kk < 2; kk++) {
            const uint32_t kb = bufo + kk * 32;
            uint32_t ah[2][4], al_[2][4];
            ldsm4(ah[0], kb + A_HI + aOff);
            ldsm4(ah[1], kb + A_HI + aOff + 16 * ROWB);
            if (ATERMS == 2) {
                ldsm4(al_[0], kb + A_LO + aOff);
                ldsm4(al_[1], kb + A_LO + aOff + 16 * ROWB);
            }
#pragma unroll
            for (int half = 0; half < 2; half++) {
                uint32_t bh[8];
                ldsm4(bh + 0, kb + B_T + bOff + (half * 2 + 0) * 16 * ROWB);
                ldsm4(bh + 4, kb + B_T + bOff + (half * 2 + 1) * 16 * ROWB);
#pragma unroll
                for (int n2 = 0; n2 < 4; n2++) {
                    const int nt = half * 4 + n2;
#pragma unroll
                    for (int mt = 0; mt < 2; mt++) {
                        mma_f16(acc[mt][nt], ah[mt], bh + n2 * 2);
                        if (ATERMS == 2) mma_f16(acc[mt][nt], al_[mt], bh + n2 * 2);
                    }
                }
            }
        }
    }

    // ---- epilogue ----
#pragma unroll
    for (int mt = 0; mt < 2; mt++) {
        const long r0 = rowBlk + warpM + mt * 16 + g;
#pragma unroll
        for (int nt = 0; nt < 8; nt++) {
            const long c = colBlk + warpN + nt * 8 + q * 2;
            float d0 = acc[mt][nt][0], d1 = acc[mt][nt][1];
            float d2 = acc[mt][nt][2], d3 = acc[mt][nt][3];
            if (EPI == 1) {
                d0 = tanhf(d0); d1 = tanhf(d1); d2 = tanhf(d2); d3 = tanhf(d3);
                __half2 H0; H0.x = __float2half(d0); H0.y = __float2half(d1);
                __half2 H2; H2.x = __float2half(d2); H2.y = __float2half(d3);
                *reinterpret_cast<uint32_t*>(Ch + r0 * N + c)       = *reinterpret_cast<uint32_t*>(&H0);
                *reinterpret_cast<uint32_t*>(Ch + (r0 + 8) * N + c) = *reinterpret_cast<uint32_t*>(&H2);
            } else {
                float2 u; u.x = d0; u.y = d1;
                float2 w; w.x = d2; w.y = d3;
                *reinterpret_cast<float2*>(Cf + r0 * N + c) = u;
                *reinterpret_cast<float2*>(Cf + (r0 + 8) * N + c) = w;
            }
        }
    }
}

// ---------------- elementwise fp32 -> fp16 hi/lo ----------------
__global__ __launch_bounds__(256) void conv_split_h(
    const float4* __restrict__ x, uint2* __restrict__ h, uint2* __restrict__ l, int n4)
{
    int i = blockIdx.x * blockDim.x + threadIdx.x;
    if (i < n4) {
        uint2 hh, ll;
        split4h(x[i], hh, ll);
        h[i] = hh; l[i] = ll;
    }
}

// ---------------- elementwise fp32 -> fp16 single ----------------
__global__ __launch_bounds__(256) void conv_round_h(
    const float4* __restrict__ x, uint2* __restrict__ h, int n4)
{
    int i = blockIdx.x * blockDim.x + threadIdx.x;
    if (i < n4) h[i] = round4h(x[i]);
}

// ---------------- V transpose + fp16 round ----------------
__global__ __launch_bounds__(256) void vtrans_kernel(
    const float* __restrict__ V, __half* __restrict__ Vh)
{
    __shared__ float t[32][33];
    const int b = blockIdx.z;
    const float* Vb = V + (long)b * LK * DM;
    const int k0 = blockIdx.x * 32, n0 = blockIdx.y * 32;
    const int tx = threadIdx.x & 31, ty = threadIdx.x >> 5;
#pragma unroll
    for (int i = 0; i < 4; i++)
        t[ty + i * 8][tx] = Vb[(long)(k0 + ty + i * 8) * DM + n0 + tx];
    __syncthreads();
    const long obase = (long)b * DM * LK;
#pragma unroll
    for (int i = 0; i < 4; i++) {
        int n = n0 + ty + i * 8, k = k0 + tx;
        Vh[obase + (long)n * LK + k] = __float2half(t[tx][ty + i * 8]);
    }
}

// ---------------- softmax: fp32 att out + fp16 att out ----------------
__global__ __launch_bounds__(256) void softmax_kernel(
    float* __restrict__ att, const int* __restrict__ kli,
    __half* __restrict__ ath)
{
    const int row = blockIdx.x;
    const int b = row >> 11;
    float* p = att + (long)row * LK;
    const int* m = kli + (long)b * LK;
    const int tid = threadIdx.x;
    const int c0 = tid * 8;
    const float scale = 0.03125f;

    float vals[8];
    {
        float4 x0 = *reinterpret_cast<const float4*>(p + c0);
        float4 x1 = *reinterpret_cast<const float4*>(p + c0 + 4);
        int4 m0 = *reinterpret_cast<const int4*>(m + c0);
        int4 m1 = *reinterpret_cast<const int4*>(m + c0 + 4);
        vals[0] = (m0.x == 0) ? -1.0e9f : x0.x * scale;
        vals[1] = (m0.y == 0) ? -1.0e9f : x0.y * scale;
        vals[2] = (m0.z == 0) ? -1.0e9f : x0.z * scale;
        vals[3] = (m0.w == 0) ? -1.0e9f : x0.w * scale;
        vals[4] = (m1.x == 0) ? -1.0e9f : x1.x * scale;
        vals[5] = (m1.y == 0) ? -1.0e9f : x1.y * scale;
        vals[6] = (m1.z == 0) ? -1.0e9f : x1.z * scale;
        vals[7] = (m1.w == 0) ? -1.0e9f : x1.w * scale;
    }

    float mx = vals[0];
#pragma unroll
    for (int i = 1; i < 8; i++) mx = fmaxf(mx, vals[i]);

    __shared__ float red[8];
#pragma unroll
    for (int o = 16; o > 0; o >>= 1)
        mx = fmaxf(mx, __shfl_xor_sync(0xffffffffu, mx, o));
    if ((tid & 31) == 0) red[tid >> 5] = mx;
    __syncthreads();
    mx = red[0];
#pragma unroll
    for (int i = 1; i < 8; i++) mx = fmaxf(mx, red[i]);
    __syncthreads();

    float sum = 0.0f;
#pragma unroll
    for (int i = 0; i < 8; i++) {
        vals[i] = expf(vals[i] - mx);
        sum += vals[i];
    }
#pragma unroll
    for (int o = 16; o > 0; o >>= 1)
        sum += __shfl_xor_sync(0xffffffffu, sum, o);
    if ((tid & 31) == 0) red[tid >> 5] = sum;
    __syncthreads();
    sum = 0.0f;
#pragma unroll
    for (int i = 0; i < 8; i++) sum += red[i];

    const float inv = 1.0f / sum;
#pragma unroll
    for (int i = 0; i < 8; i++) vals[i] *= inv;

    float4 y0; y0.x = vals[0]; y0.y = vals[1]; y0.z = vals[2]; y0.w = vals[3];
    float4 y1; y1.x = vals[4]; y1.y = vals[5]; y1.z = vals[6]; y1.w = vals[7];
    *reinterpret_cast<float4*>(p + c0) = y0;
    *reinterpret_cast<float4*>(p + c0 + 4) = y1;

    uint2 h0 = round4h(y0);
    uint2 h1 = round4h(y1);
    uint4 H; H.x = h0.x; H.y = h0.y; H.z = h1.x; H.w = h1.y;
    *reinterpret_cast<uint4*>(ath + (long)row * LK + c0) = H;
}

// ---------------- launch ----------------
extern "C" void kernel_launch(void* const* d_in, const int* in_sizes, int n_in,
                              void* d_out, int out_size)
{
    const float* q   = (const float*)d_in[0];   // [B, Lq, Dq]
    const float* k   = (const float*)d_in[1];   // [B, Lk, Dk]
    const float* v   = (const float*)d_in[2];   // [B, Lk, Dv]
    const int*   kli = (const int*)  d_in[3];   // [B, Lk]
    const float* W   = (const float*)d_in[4];   // [Dq, Dk]

    float* out = (float*)d_out;                            // [B, Lq, Dv]
    float* att = out + (size_t)BATCH * LQ * DM;            // [B, Lq, Lk]

    __half *qh, *ql, *kh, *wh, *kth, *vth, *ath;
    cudaGetSymbolAddress((void**)&qh, g_qh);   cudaGetSymbolAddress((void**)&ql, g_ql);
    cudaGetSymbolAddress((void**)&kh, g_kh);
    cudaGetSymbolAddress((void**)&wh, g_wh);
    cudaGetSymbolAddress((void**)&kth, g_kth);
    cudaGetSymbolAddress((void**)&vth, g_vth);
    cudaGetSymbolAddress((void**)&ath, g_ath);

    const int SM2 = NSTAGE * 3 * TILE_B;   // 2-term stages: 92160
    const int SM1 = NSTAGE * 2 * TILE_B;   // 1-term stages: 61440
    cudaFuncSetAttribute(gemm_h<1, 1>, cudaFuncAttributeMaxDynamicSharedMemorySize, SM1);
    cudaFuncSetAttribute(gemm_h<0, 2>, cudaFuncAttributeMaxDynamicSharedMemorySize, SM2);
    cudaFuncSetAttribute(gemm_h<0, 1>, cudaFuncAttributeMaxDynamicSharedMemorySize, SM1);

    // 0) preconvert operands
    const int nQK4 = BATCH * LQ * DM / 4;
    conv_split_h<<<nQK4 / 256, 256>>>((const float4*)q, (uint2*)qh, (uint2*)ql, nQK4);
    conv_round_h<<<nQK4 / 256, 256>>>((const float4*)k, (uint2*)kh, nQK4);
    const int nW4 = DM * DM / 4;
    conv_round_h<<<nW4 / 256, 256>>>((const float4*)W, (uint2*)wh, nW4);
    vtrans_kernel<<<dim3(LK / 32, DM / 32, BATCH), 256>>>(v, vth);

    // 1) kt = tanh(K @ W^T) -> fp16. 1-term A. M=Lk, N=Dq, K=Dk. W broadcast.
    gemm_h<1, 1><<<dim3(DM / BN, LK / BM, BATCH), NTH, SM1>>>(
        kh, nullptr, wh, nullptr, kth,
        LK, DM, DM, (long)LK * DM, 0L, (long)LK * DM);

    // 2) scores = Q @ kt^T -> att (fp32). 2-term A. M=Lq, N=Lk, K=Dq.
    gemm_h<0, 2><<<dim3(LK / BN, LQ / BM, BATCH), NTH, SM2>>>(
        qh, ql, kth, att, nullptr,
        LQ, LK, DM, (long)LQ * DM, (long)LK * DM, (long)LQ * LK);

    // 3) softmax in place + emit fp16 att
    softmax_kernel<<<BATCH * LQ, 256>>>(att, kli, ath);

    // 4) out = att @ V. 1-term A. M=Lq, N=Dv, K=Lk.
    gemm_h<0, 1><<<dim3(DM / BN, LQ / BM, BATCH), NTH, SM1>>>(
        ath, nullptr, vth, out, nullptr,
        LQ, DM, LK, (long)LQ * LK, (long)DM * LK, (long)LQ * DM);
}

// round 9
// speedup vs baseline: 5.7989x; 1.2215x over previous
#include <cuda_runtime.h>
#include <cuda_fp16.h>
#include <math.h>
#include <stdint.h>

// Problem shape (fixed): B=16, Lq=Lk=2048, Dq=Dk=Dv=1024
#define BATCH 16
#define LQ 2048
#define LK 2048
#define DM 1024

// GEMM tiling
#define BM 128
#define BN 128
#define BK 32
#define NTH 256

// smem: K-major fp16 tiles, 64B data rows padded to 80B (conflict-free LDSM)
#define ROWB 80
#define TILE_B (128 * ROWB)          // 10240
#define NSTAGE 3

// ---------------- device scratch (preconverted fp16 operands) ----------------
__device__ __half g_qh[(size_t)BATCH * LQ * DM];    // Q single fp16
__device__ __half g_kh[(size_t)BATCH * LK * DM];    // K single fp16
__device__ __half g_wh[(size_t)DM * DM];            // W single fp16
__device__ __half g_kth[(size_t)BATCH * LK * DM];   // tanh(K W^T) single fp16
__device__ __half g_vth[(size_t)BATCH * DM * LK];   // V^T single fp16
__device__ __half g_ath[(size_t)BATCH * LQ * LK];   // att single fp16

// ---------------- helpers ----------------
__device__ __forceinline__ uint2 round4h(float4 v) {
    __half2 H01; H01.x = __float2half(v.x); H01.y = __float2half(v.y);
    __half2 H23; H23.x = __float2half(v.z); H23.y = __float2half(v.w);
    uint2 r;
    r.x = *reinterpret_cast<uint32_t*>(&H01);
    r.y = *reinterpret_cast<uint32_t*>(&H23);
    return r;
}

__device__ __forceinline__ void mma_f16(float* d, const uint32_t* a, const uint32_t* b) {
    asm volatile(
        "mma.sync.aligned.m16n8k16.row.col.f32.f16.f16.f32 "
        "{%0,%1,%2,%3},{%4,%5,%6,%7},{%8,%9},{%0,%1,%2,%3};"
        : "+f"(d[0]), "+f"(d[1]), "+f"(d[2]), "+f"(d[3])
        : "r"(a[0]), "r"(a[1]), "r"(a[2]), "r"(a[3]), "r"(b[0]), "r"(b[1]));
}

__device__ __forceinline__ void ldsm4(uint32_t* r, uint32_t a) {
    asm volatile("ldmatrix.sync.aligned.m8n8.x4.shared.b16 {%0,%1,%2,%3}, [%4];"
                 : "=r"(r[0]), "=r"(r[1]), "=r"(r[2]), "=r"(r[3]) : "r"(a));
}

__device__ __forceinline__ void cpasync16(uint32_t dst, const void* src) {
    asm volatile("cp.async.cg.shared.global [%0], [%1], 16;" :: "r"(dst), "l"(src));
}
__device__ __forceinline__ void cp_commit() {
    asm volatile("cp.async.commit_group;" ::: "memory");
}
__device__ __forceinline__ void cp_wait1() {
    asm volatile("cp.async.wait_group 1;" ::: "memory");
}
__device__ __forceinline__ void cp_wait0() {
    asm volatile("cp.async.wait_group 0;" ::: "memory");
}

// ------------- GEMM: C[M,N] = A[M,K] * B[N,K]^T, 1-term fp16 HMMA -------------
// EPI=0: fp32 out.  EPI=1: tanh -> fp16 out.
template <int EPI>
__global__ __launch_bounds__(NTH, 2)
void gemm_h(const __half* __restrict__ Ah, const __half* __restrict__ Bh,
            float* __restrict__ Cf, __half* __restrict__ Ch,
            int M, int N, int K, long sA, long sB, long sC)
{
    constexpr uint32_t A_T = 0;
    constexpr uint32_t B_T = TILE_B;
    constexpr uint32_t STAGE_SZ = 2 * TILE_B;

    extern __shared__ char sm[];
    const uint32_t usm = (uint32_t)__cvta_generic_to_shared(sm);

    const int tid = threadIdx.x;
    const int wid = tid >> 5;
    const int lane = tid & 31;
    const int g = lane >> 2;
    const int q = lane & 3;
    const int warpM = (wid & 3) * 32;
    const int warpN = (wid >> 2) * 64;

    const int bz = blockIdx.z;
    Ah += (long)bz * sA;
    Bh += (long)bz * sB;
    if (EPI == 0) Cf += (long)bz * sC; else Ch += (long)bz * sC;

    const int rowBlk = blockIdx.y * BM;
    const int colBlk = blockIdx.x * BN;

    float acc[2][8][4];
#pragma unroll
    for (int mt = 0; mt < 2; mt++)
#pragma unroll
        for (int nt = 0; nt < 8; nt++)
#pragma unroll
            for (int j = 0; j < 4; j++) acc[mt][nt][j] = 0.0f;

    // ldmatrix lane addressing
    const int jj = lane >> 3, lr = lane & 7;
    const uint32_t aOff = (uint32_t)((warpM + (jj & 1) * 8 + lr) * ROWB + (jj >> 1) * 16);
    const uint32_t bOff = (uint32_t)((warpN + (jj >> 1) * 8 + lr) * ROWB + (jj & 1) * 16);

    const int S = K / BK;

    // loader: 4 cp.async per thread (A 512 chunks + B 512 chunks of 16B)
    auto load_stage = [&](int s, uint32_t bufo) {
        const int k0 = s * BK;
#pragma unroll
        for (int i = 0; i < 4; i++) {
            const int comp = i >> 1;               // 0=A, 1=B
            const int w = tid + (i & 1) * NTH;     // 0..511
            const int r = w >> 2, ch = w & 3;
            const uint32_t dst = usm + bufo + comp * TILE_B + r * ROWB + ch * 16;
            const __half* src = comp ? Bh : Ah;
            const long row = (comp ? colBlk : rowBlk) + r;
            cpasync16(dst, src + row * (long)K + k0 + ch * 8);
        }
    };

    // prologue: stages 0,1
    load_stage(0, 0);
    cp_commit();
    if (S > 1) { load_stage(1, STAGE_SZ); }
    cp_commit();

    for (int s = 0; s < S; s++) {
        if (s + 1 < S) cp_wait1(); else cp_wait0();
        __syncthreads();

        if (s + 2 < S) { load_stage(s + 2, (uint32_t)(((s + 2) % NSTAGE) * STAGE_SZ)); }
        cp_commit();

        const uint32_t bufo = usm + (uint32_t)((s % NSTAGE) * STAGE_SZ);
#pragma unroll
        for (int kk = 0; kk < 2; kk++) {
            const uint32_t kb = bufo + kk * 32;
            uint32_t ah[2][4];
            ldsm4(ah[0], kb + A_T + aOff);
            ldsm4(ah[1], kb + A_T + aOff + 16 * ROWB);
#pragma unroll
            for (int half = 0; half < 2; half++) {
                uint32_t bh[8];
                ldsm4(bh + 0, kb + B_T + bOff + (half * 2 + 0) * 16 * ROWB);
                ldsm4(bh + 4, kb + B_T + bOff + (half * 2 + 1) * 16 * ROWB);
#pragma unroll
                for (int n2 = 0; n2 < 4; n2++) {
                    const int nt = half * 4 + n2;
#pragma unroll
                    for (int mt = 0; mt < 2; mt++)
                        mma_f16(acc[mt][nt], ah[mt], bh + n2 * 2);
                }
            }
        }
    }

    // ---- epilogue ----
#pragma unroll
    for (int mt = 0; mt < 2; mt++) {
        const long r0 = rowBlk + warpM + mt * 16 + g;
#pragma unroll
        for (int nt = 0; nt < 8; nt++) {
            const long c = colBlk + warpN + nt * 8 + q * 2;
            float d0 = acc[mt][nt][0], d1 = acc[mt][nt][1];
            float d2 = acc[mt][nt][2], d3 = acc[mt][nt][3];
            if (EPI == 1) {
                d0 = tanhf(d0); d1 = tanhf(d1); d2 = tanhf(d2); d3 = tanhf(d3);
                __half2 H0; H0.x = __float2half(d0); H0.y = __float2half(d1);
                __half2 H2; H2.x = __float2half(d2); H2.y = __float2half(d3);
                *reinterpret_cast<uint32_t*>(Ch + r0 * N + c)       = *reinterpret_cast<uint32_t*>(&H0);
                *reinterpret_cast<uint32_t*>(Ch + (r0 + 8) * N + c) = *reinterpret_cast<uint32_t*>(&H2);
            } else {
                float2 u; u.x = d0; u.y = d1;
                float2 w; w.x = d2; w.y = d3;
                *reinterpret_cast<float2*>(Cf + r0 * N + c) = u;
                *reinterpret_cast<float2*>(Cf + (r0 + 8) * N + c) = w;
            }
        }
    }
}

// ---------------- elementwise fp32 -> fp16 ----------------
__global__ __launch_bounds__(256) void conv_round_h(
    const float4* __restrict__ x, uint2* __restrict__ h, int n4)
{
    int i = blockIdx.x * blockDim.x + threadIdx.x;
    if (i < n4) h[i] = round4h(x[i]);
}

// ---------------- V transpose + fp16 round ----------------
__global__ __launch_bounds__(256) void vtrans_kernel(
    const float* __restrict__ V, __half* __restrict__ Vh)
{
    __shared__ float t[32][33];
    const int b = blockIdx.z;
    const float* Vb = V + (long)b * LK * DM;
    const int k0 = blockIdx.x * 32, n0 = blockIdx.y * 32;
    const int tx = threadIdx.x & 31, ty = threadIdx.x >> 5;
#pragma unroll
    for (int i = 0; i < 4; i++)
        t[ty + i * 8][tx] = Vb[(long)(k0 + ty + i * 8) * DM + n0 + tx];
    __syncthreads();
    const long obase = (long)b * DM * LK;
#pragma unroll
    for (int i = 0; i < 4; i++) {
        int n = n0 + ty + i * 8, k = k0 + tx;
        Vh[obase + (long)n * LK + k] = __float2half(t[tx][ty + i * 8]);
    }
}

// ---------------- softmax: fp32 att out + fp16 att out ----------------
__global__ __launch_bounds__(256) void softmax_kernel(
    float* __restrict__ att, const int* __restrict__ kli,
    __half* __restrict__ ath)
{
    const int row = blockIdx.x;
    const int b = row >> 11;
    float* p = att + (long)row * LK;
    const int* m = kli + (long)b * LK;
    const int tid = threadIdx.x;
    const int c0 = tid * 8;
    const float scale = 0.03125f;

    float vals[8];
    {
        float4 x0 = *reinterpret_cast<const float4*>(p + c0);
        float4 x1 = *reinterpret_cast<const float4*>(p + c0 + 4);
        int4 m0 = *reinterpret_cast<const int4*>(m + c0);
        int4 m1 = *reinterpret_cast<const int4*>(m + c0 + 4);
        vals[0] = (m0.x == 0) ? -1.0e9f : x0.x * scale;
        vals[1] = (m0.y == 0) ? -1.0e9f : x0.y * scale;
        vals[2] = (m0.z == 0) ? -1.0e9f : x0.z * scale;
        vals[3] = (m0.w == 0) ? -1.0e9f : x0.w * scale;
        vals[4] = (m1.x == 0) ? -1.0e9f : x1.x * scale;
        vals[5] = (m1.y == 0) ? -1.0e9f : x1.y * scale;
        vals[6] = (m1.z == 0) ? -1.0e9f : x1.z * scale;
        vals[7] = (m1.w == 0) ? -1.0e9f : x1.w * scale;
    }

    float mx = vals[0];
#pragma unroll
    for (int i = 1; i < 8; i++) mx = fmaxf(mx, vals[i]);

    __shared__ float red[8];
#pragma unroll
    for (int o = 16; o > 0; o >>= 1)
        mx = fmaxf(mx, __shfl_xor_sync(0xffffffffu, mx, o));
    if ((tid & 31) == 0) red[tid >> 5] = mx;
    __syncthreads();
    mx = red[0];
#pragma unroll
    for (int i = 1; i < 8; i++) mx = fmaxf(mx, red[i]);
    __syncthreads();

    float sum = 0.0f;
#pragma unroll
    for (int i = 0; i < 8; i++) {
        vals[i] = expf(vals[i] - mx);
        sum += vals[i];
    }
#pragma unroll
    for (int o = 16; o > 0; o >>= 1)
        sum += __shfl_xor_sync(0xffffffffu, sum, o);
    if ((tid & 31) == 0) red[tid >> 5] = sum;
    __syncthreads();
    sum = 0.0f;
#pragma unroll
    for (int i = 0; i < 8; i++) sum += red[i];

    const float inv = 1.0f / sum;
#pragma unroll
    for (int i = 0; i < 8; i++) vals[i] *= inv;

    float4 y0; y0.x = vals[0]; y0.y = vals[1]; y0.z = vals[2]; y0.w = vals[3];
    float4 y1; y1.x = vals[4]; y1.y = vals[5]; y1.z = vals[6]; y1.w = vals[7];
    *reinterpret_cast<float4*>(p + c0) = y0;
    *reinterpret_cast<float4*>(p + c0 + 4) = y1;

    uint2 h0 = round4h(y0);
    uint2 h1 = round4h(y1);
    uint4 H; H.x = h0.x; H.y = h0.y; H.z = h1.x; H.w = h1.y;
    *reinterpret_cast<uint4*>(ath + (long)row * LK + c0) = H;
}

// ---------------- launch ----------------
extern "C" void kernel_launch(void* const* d_in, const int* in_sizes, int n_in,
                              void* d_out, int out_size)
{
    const float* q   = (const float*)d_in[0];   // [B, Lq, Dq]
    const float* k   = (const float*)d_in[1];   // [B, Lk, Dk]
    const float* v   = (const float*)d_in[2];   // [B, Lk, Dv]
    const int*   kli = (const int*)  d_in[3];   // [B, Lk]
    const float* W   = (const float*)d_in[4];   // [Dq, Dk]

    float* out = (float*)d_out;                            // [B, Lq, Dv]
    float* att = out + (size_t)BATCH * LQ * DM;            // [B, Lq, Lk]

    __half *qh, *kh, *wh, *kth, *vth, *ath;
    cudaGetSymbolAddress((void**)&qh, g_qh);
    cudaGetSymbolAddress((void**)&kh, g_kh);
    cudaGetSymbolAddress((void**)&wh, g_wh);
    cudaGetSymbolAddress((void**)&kth, g_kth);
    cudaGetSymbolAddress((void**)&vth, g_vth);
    cudaGetSymbolAddress((void**)&ath, g_ath);

    const int SM1 = NSTAGE * 2 * TILE_B;   // 61440
    cudaFuncSetAttribute(gemm_h<0>, cudaFuncAttributeMaxDynamicSharedMemorySize, SM1);
    cudaFuncSetAttribute(gemm_h<1>, cudaFuncAttributeMaxDynamicSharedMemorySize, SM1);

    // 0) preconvert operands
    const int nQK4 = BATCH * LQ * DM / 4;
    conv_round_h<<<nQK4 / 256, 256>>>((const float4*)q, (uint2*)qh, nQK4);
    conv_round_h<<<nQK4 / 256, 256>>>((const float4*)k, (uint2*)kh, nQK4);
    const int nW4 = DM * DM / 4;
    conv_round_h<<<nW4 / 256, 256>>>((const float4*)W, (uint2*)wh, nW4);
    vtrans_kernel<<<dim3(LK / 32, DM / 32, BATCH), 256>>>(v, vth);

    // 1) kt = tanh(K @ W^T) -> fp16. M=Lk, N=Dq, K=Dk. W broadcast.
    gemm_h<1><<<dim3(DM / BN, LK / BM, BATCH), NTH, SM1>>>(
        kh, wh, nullptr, kth,
        LK, DM, DM, (long)LK * DM, 0L, (long)LK * DM);

    // 2) scores = Q @ kt^T -> att (fp32). M=Lq, N=Lk, K=Dq.
    gemm_h<0><<<dim3(LK / BN, LQ / BM, BATCH), NTH, SM1>>>(
        qh, kth, att, nullptr,
        LQ, LK, DM, (long)LQ * DM, (long)LK * DM, (long)LQ * LK);

    // 3) softmax in place + emit fp16 att
    softmax_kernel<<<BATCH * LQ, 256>>>(att, kli, ath);

    // 4) out = att @ V. M=Lq, N=Dv, K=Lk.
    gemm_h<0><<<dim3(DM / BN, LQ / BM, BATCH), NTH, SM1>>>(
        ath, vth, out, nullptr,
        LQ, DM, LK, (long)LQ * LK, (long)DM * LK, (long)LQ * DM);
}